// round 3
// baseline (speedup 1.0000x reference)
#include <cuda_runtime.h>
#include <math.h>
#include <stdint.h>

#define TSEQ   2048
#define DMODEL 1024
#define NH     16
#define HDIM   64
#define BATCH  2
#define BH     (BATCH*NH)   // 32

// ---------------- scratch (static device arrays; no allocation) ----------------
__device__ float g_F[(size_t)TSEQ * DMODEL];            // 8 MB  : F[d][dim] = PE(pos=d)
__device__ float g_Q[(size_t)BH * TSEQ * HDIM];         // 16 MB : [b,h,t,hd]
__device__ float g_Km[(size_t)BH * TSEQ * HDIM];        // 16 MB
__device__ float g_V[(size_t)BH * TSEQ * HDIM];         // 16 MB
__device__ float g_ctx[(size_t)BATCH * TSEQ * DMODEL];  // 16 MB
// fallback scratch in case d_out does not include the score tensor
__device__ float g_scoreScratch[(size_t)BH * TSEQ * TSEQ];

// ---------------- 1) relative PE table: F[d][dim] ----------------
// reference: pe row l uses pos=T-1-l; att_e needs E[T-1-(q-k)] => F[d] uses pos=d.
__global__ void pe_kernel() {
    int idx = blockIdx.x * 256 + threadIdx.x;        // T*D = 2M threads
    int d   = idx >> 10;                             // / DMODEL
    int dim = idx & (DMODEL - 1);
    int i2  = dim & ~1;
    float div = __expf(-9.210340371976184f * (float)i2 * (1.0f / (float)DMODEL));
    float ang = (float)d * div;
    g_F[idx] = (dim & 1) ? cosf(ang) : sinf(ang);
}

// ---------------- 2) QKV GEMM: [4096,1024] x [1024,3072], scatter to Q/K/V ----------------
__global__ void __launch_bounds__(256, 2) qkv_gemm(const float* __restrict__ X,
                                                   const float* __restrict__ W) {
    __shared__ float As[16][128];   // As[k][m]
    __shared__ float Bs[16][128];   // Bs[k][n]
    int bm = blockIdx.y * 128;
    int bn = blockIdx.x * 128;
    int tid = threadIdx.x;
    int tx = tid & 15, ty = tid >> 4;

    float acc[8][8];
#pragma unroll
    for (int i = 0; i < 8; i++)
#pragma unroll
        for (int j = 0; j < 8; j++) acc[i][j] = 0.f;

    for (int k0 = 0; k0 < 1024; k0 += 16) {
#pragma unroll
        for (int it = 0; it < 2; it++) {
            int idx = tid + it * 256;        // 0..511
            int r = idx >> 2;                // 0..127
            int c4 = idx & 3;                // 0..3
            float4 v = *(const float4*)&X[(size_t)(bm + r) * 1024 + k0 + c4 * 4];
            As[c4 * 4 + 0][r] = v.x; As[c4 * 4 + 1][r] = v.y;
            As[c4 * 4 + 2][r] = v.z; As[c4 * 4 + 3][r] = v.w;
        }
#pragma unroll
        for (int it = 0; it < 2; it++) {
            int idx = tid + it * 256;
            int r = idx >> 5;                // 0..15
            int c4 = idx & 31;               // 0..31
            *(float4*)&Bs[r][c4 * 4] =
                *(const float4*)&W[(size_t)(k0 + r) * 3072 + bn + c4 * 4];
        }
        __syncthreads();
#pragma unroll
        for (int kk = 0; kk < 16; kk++) {
            float4 a0 = *(float4*)&As[kk][ty * 8];
            float4 a1 = *(float4*)&As[kk][ty * 8 + 4];
            float4 b0 = *(float4*)&Bs[kk][tx * 8];
            float4 b1 = *(float4*)&Bs[kk][tx * 8 + 4];
            float a[8] = {a0.x, a0.y, a0.z, a0.w, a1.x, a1.y, a1.z, a1.w};
            float b[8] = {b0.x, b0.y, b0.z, b0.w, b1.x, b1.y, b1.z, b1.w};
#pragma unroll
            for (int i = 0; i < 8; i++)
#pragma unroll
                for (int j = 0; j < 8; j++) acc[i][j] = fmaf(a[i], b[j], acc[i][j]);
        }
        __syncthreads();
    }

    // epilogue: scatter to [b,h,t,hd] layout
    int nbase = bn + tx * 8;               // aligned to 8; stays within one sect & one head
    int sect = nbase >> 10;
    int d0 = nbase & 1023;
    int h = d0 >> 6;
    int hd = d0 & 63;
    float* dst = (sect == 0) ? g_Q : ((sect == 1) ? g_Km : g_V);
#pragma unroll
    for (int i = 0; i < 8; i++) {
        int m = bm + ty * 8 + i;
        int b = m >> 11, t = m & 2047;
        float* p = &dst[(((size_t)b * NH + h) * TSEQ + t) * HDIM + hd];
        *(float4*)&p[0] = make_float4(acc[i][0], acc[i][1], acc[i][2], acc[i][3]);
        *(float4*)&p[4] = make_float4(acc[i][4], acc[i][5], acc[i][6], acc[i][7]);
    }
}

// ---------------- 3) fused causal logits: (Q.K^T + Q.F[q-k]) / 8 ----------------
// 64x64 tiles, HD split into two halves of 32 to keep smem at 32 KB.
__global__ void __launch_bounds__(256) logits_kernel(float* __restrict__ score) {
    int bn = blockIdx.x;      // k tile
    int bm = blockIdx.y;      // q tile
    if (bn > bm) return;      // fully masked tile
    int z = blockIdx.z;       // b*H + h
    int h = z & (NH - 1);

    __shared__ float Qs[32][64];    // [hd][q]
    __shared__ float Ks[32][64];    // [hd][k]
    __shared__ float Fs[32][128];   // [hd][band row]; rows 0..126 used

    int tid = threadIdx.x;
    int tx = tid & 15, ty = tid >> 4;

    float acc[4][4];
#pragma unroll
    for (int i = 0; i < 4; i++)
#pragma unroll
        for (int j = 0; j < 4; j++) acc[i][j] = 0.f;

    const float* Qg = &g_Q[((size_t)z * TSEQ + bm * 64) * HDIM];
    const float* Kg = &g_Km[((size_t)z * TSEQ + bn * 64) * HDIM];
    int dtile = (bm - bn) * 64;
    int r0 = 4 * (ty - tx) + 60;    // 0..120, 4-aligned

    for (int half = 0; half < 2; half++) {
        int hoff = half * 32;
        // load Q, K tiles (64 rows x 32 cols) transposed into smem
#pragma unroll
        for (int it = 0; it < 2; it++) {
            int idx = tid + it * 256;    // 0..511
            int r = idx >> 3;            // 0..63
            int c4 = idx & 7;            // 0..7
            float4 q4 = *(const float4*)&Qg[(size_t)r * HDIM + hoff + c4 * 4];
            Qs[c4 * 4 + 0][r] = q4.x; Qs[c4 * 4 + 1][r] = q4.y;
            Qs[c4 * 4 + 2][r] = q4.z; Qs[c4 * 4 + 3][r] = q4.w;
            float4 k4 = *(const float4*)&Kg[(size_t)r * HDIM + hoff + c4 * 4];
            Ks[c4 * 4 + 0][r] = k4.x; Ks[c4 * 4 + 1][r] = k4.y;
            Ks[c4 * 4 + 2][r] = k4.z; Ks[c4 * 4 + 3][r] = k4.w;
        }
        // load F band: band row r <-> d = dtile - 63 + r, r = 0..126
        for (int idx = tid; idx < 127 * 8; idx += 256) {
            int r = idx >> 3;
            int c4 = idx & 7;
            int d = dtile - 63 + r;
            float4 f4 = make_float4(0.f, 0.f, 0.f, 0.f);
            if (d >= 0 && d < TSEQ)
                f4 = *(const float4*)&g_F[(size_t)d * DMODEL + h * HDIM + hoff + c4 * 4];
            Fs[c4 * 4 + 0][r] = f4.x; Fs[c4 * 4 + 1][r] = f4.y;
            Fs[c4 * 4 + 2][r] = f4.z; Fs[c4 * 4 + 3][r] = f4.w;
        }
        __syncthreads();

#pragma unroll
        for (int hc = 0; hc < 32; hc++) {
            float4 av = *(float4*)&Qs[hc][ty * 4];
            float4 bv = *(float4*)&Ks[hc][tx * 4];
            float4 f0 = *(float4*)&Fs[hc][r0];
            float4 f1 = *(float4*)&Fs[hc][r0 + 4];
            float a[4]  = {av.x, av.y, av.z, av.w};
            float b4[4] = {bv.x, bv.y, bv.z, bv.w};
            float fv[7] = {f0.x, f0.y, f0.z, f0.w, f1.x, f1.y, f1.z}; // band row r0+c, c=i-j+3
#pragma unroll
            for (int i = 0; i < 4; i++)
#pragma unroll
                for (int j = 0; j < 4; j++) {
                    acc[i][j] = fmaf(a[i], b4[j], acc[i][j]);
                    acc[i][j] = fmaf(a[i], fv[i - j + 3], acc[i][j]);
                }
        }
        __syncthreads();
    }

    const float inv_scale = 0.125f;   // 1/sqrt(64)
    size_t base = ((size_t)z * TSEQ + bm * 64 + ty * 4) * TSEQ + bn * 64 + tx * 4;
#pragma unroll
    for (int i = 0; i < 4; i++) {
        *(float4*)&score[base + (size_t)i * TSEQ] =
            make_float4(acc[i][0] * inv_scale, acc[i][1] * inv_scale,
                        acc[i][2] * inv_scale, acc[i][3] * inv_scale);
    }
}

// ---------------- 4) causal row softmax, in-place on score; zeros for k>q ----------------
__global__ void __launch_bounds__(256) softmax_kernel(float* __restrict__ score) {
    size_t row = blockIdx.x;                 // 0 .. BH*T-1
    int q = (int)(row & (TSEQ - 1));
    float* p = &score[row * TSEQ];
    int tid = threadIdx.x;

    __shared__ float red[8];
    float v[8];
    float mx = -1e30f;
#pragma unroll
    for (int i = 0; i < 8; i++) {
        int k = i * 256 + tid;
        v[i] = (k <= q) ? p[k] : -1e30f;
        mx = fmaxf(mx, v[i]);
    }
#pragma unroll
    for (int o = 16; o > 0; o >>= 1) mx = fmaxf(mx, __shfl_xor_sync(0xffffffffu, mx, o));
    if ((tid & 31) == 0) red[tid >> 5] = mx;
    __syncthreads();
    float bmx = red[0];
#pragma unroll
    for (int w = 1; w < 8; w++) bmx = fmaxf(bmx, red[w]);

    float s = 0.f;
#pragma unroll
    for (int i = 0; i < 8; i++) {
        int k = i * 256 + tid;
        float e = (k <= q) ? __expf(v[i] - bmx) : 0.f;
        v[i] = e;
        s += e;
    }
#pragma unroll
    for (int o = 16; o > 0; o >>= 1) s += __shfl_xor_sync(0xffffffffu, s, o);
    __syncthreads();                         // everyone done reading red (max)
    if ((tid & 31) == 0) red[tid >> 5] = s;
    __syncthreads();
    float tot = 0.f;
#pragma unroll
    for (int w = 0; w < 8; w++) tot += red[w];
    float inv = 1.0f / tot;
#pragma unroll
    for (int i = 0; i < 8; i++) {
        int k = i * 256 + tid;
        p[k] = v[i] * inv;                   // exact 0 for k>q
    }
}

// ---------------- 5) ctx = S @ V (causal), write [b,t,h*64+hd] ----------------
__global__ void __launch_bounds__(256) sv_kernel(const float* __restrict__ score) {
    int bm = blockIdx.y;        // q tile (0..31)
    int z = blockIdx.z;         // 0..31
    int b = z >> 4, h = z & (NH - 1);

    __shared__ float Ss[64][68];   // [q][k]
    __shared__ float Vs[64][68];   // [k][hd]
    int tid = threadIdx.x;
    int tx = tid & 15, ty = tid >> 4;

    float acc[4][4];
#pragma unroll
    for (int i = 0; i < 4; i++)
#pragma unroll
        for (int j = 0; j < 4; j++) acc[i][j] = 0.f;

    const float* Sg = &score[((size_t)z * TSEQ + bm * 64) * TSEQ];
    const float* Vg = &g_V[(size_t)z * TSEQ * HDIM];

    for (int kt = 0; kt <= bm; kt++) {
#pragma unroll
        for (int it = 0; it < 4; it++) {
            int idx = tid + it * 256;     // 0..1023
            int r = idx >> 4;             // 0..63
            int c4 = idx & 15;            // 0..15
            *(float4*)&Ss[r][c4 * 4] =
                *(const float4*)&Sg[(size_t)r * TSEQ + kt * 64 + c4 * 4];
            *(float4*)&Vs[r][c4 * 4] =
                *(const float4*)&Vg[(size_t)(kt * 64 + r) * HDIM + c4 * 4];
        }
        __syncthreads();
#pragma unroll
        for (int kk = 0; kk < 64; kk++) {
            float a[4];
#pragma unroll
            for (int i = 0; i < 4; i++) a[i] = Ss[ty * 4 + i][kk];
            float4 bv = *(float4*)&Vs[kk][tx * 4];
            float b4[4] = {bv.x, bv.y, bv.z, bv.w};
#pragma unroll
            for (int i = 0; i < 4; i++)
#pragma unroll
                for (int j = 0; j < 4; j++) acc[i][j] = fmaf(a[i], b4[j], acc[i][j]);
        }
        __syncthreads();
    }
#pragma unroll
    for (int i = 0; i < 4; i++) {
        int t = bm * 64 + ty * 4 + i;
        *(float4*)&g_ctx[((size_t)b * TSEQ + t) * DMODEL + h * HDIM + tx * 4] =
            make_float4(acc[i][0], acc[i][1], acc[i][2], acc[i][3]);
    }
}

// ---------------- 6) out = ctx @ Wout + bout ----------------
__global__ void __launch_bounds__(256, 2) outproj_gemm(const float* __restrict__ W,
                                                       const float* __restrict__ bias,
                                                       float* __restrict__ out) {
    __shared__ float As[16][128];
    __shared__ float Bs[16][128];
    int bm = blockIdx.y * 128;
    int bn = blockIdx.x * 128;
    int tid = threadIdx.x;
    int tx = tid & 15, ty = tid >> 4;

    float acc[8][8];
#pragma unroll
    for (int i = 0; i < 8; i++)
#pragma unroll
        for (int j = 0; j < 8; j++) acc[i][j] = 0.f;

    for (int k0 = 0; k0 < 1024; k0 += 16) {
#pragma unroll
        for (int it = 0; it < 2; it++) {
            int idx = tid + it * 256;
            int r = idx >> 2;
            int c4 = idx & 3;
            float4 v = *(const float4*)&g_ctx[(size_t)(bm + r) * 1024 + k0 + c4 * 4];
            As[c4 * 4 + 0][r] = v.x; As[c4 * 4 + 1][r] = v.y;
            As[c4 * 4 + 2][r] = v.z; As[c4 * 4 + 3][r] = v.w;
        }
#pragma unroll
        for (int it = 0; it < 2; it++) {
            int idx = tid + it * 256;
            int r = idx >> 5;
            int c4 = idx & 31;
            *(float4*)&Bs[r][c4 * 4] =
                *(const float4*)&W[(size_t)(k0 + r) * 1024 + bn + c4 * 4];
        }
        __syncthreads();
#pragma unroll
        for (int kk = 0; kk < 16; kk++) {
            float4 a0 = *(float4*)&As[kk][ty * 8];
            float4 a1 = *(float4*)&As[kk][ty * 8 + 4];
            float4 b0 = *(float4*)&Bs[kk][tx * 8];
            float4 b1 = *(float4*)&Bs[kk][tx * 8 + 4];
            float a[8] = {a0.x, a0.y, a0.z, a0.w, a1.x, a1.y, a1.z, a1.w};
            float b[8] = {b0.x, b0.y, b0.z, b0.w, b1.x, b1.y, b1.z, b1.w};
#pragma unroll
            for (int i = 0; i < 8; i++)
#pragma unroll
                for (int j = 0; j < 8; j++) acc[i][j] = fmaf(a[i], b[j], acc[i][j]);
        }
        __syncthreads();
    }

    float bb[8];
#pragma unroll
    for (int j = 0; j < 8; j++) bb[j] = bias[bn + tx * 8 + j];
#pragma unroll
    for (int i = 0; i < 8; i++) {
        int m = bm + ty * 8 + i;
        float* p = &out[(size_t)m * 1024 + bn + tx * 8];
        *(float4*)&p[0] = make_float4(acc[i][0] + bb[0], acc[i][1] + bb[1],
                                      acc[i][2] + bb[2], acc[i][3] + bb[3]);
        *(float4*)&p[4] = make_float4(acc[i][4] + bb[4], acc[i][5] + bb[5],
                                      acc[i][6] + bb[6], acc[i][7] + bb[7]);
    }
}

// ---------------- launch ----------------
extern "C" void kernel_launch(void* const* d_in, const int* in_sizes, int n_in,
                              void* d_out, int out_size) {
    const float* x    = (const float*)d_in[0];   // [B,T,D]
    // d_in[1] = mask (known causal, unused)
    const float* Wqkv = (const float*)d_in[2];   // [D,3D]
    const float* Wout = (const float*)d_in[3];   // [D,D]
    const float* bout = (const float*)d_in[4];   // [D]

    float* out = (float*)d_out;
    const size_t outElems = (size_t)BATCH * TSEQ * DMODEL;           // 4,194,304
    const size_t scoreElems = (size_t)BH * TSEQ * TSEQ;              // 134,217,728
    float* score = ((size_t)out_size >= outElems + scoreElems)
                       ? (out + outElems)
                       : g_scoreScratch;   // defensive: layout without score output

    pe_kernel<<<(TSEQ * DMODEL) / 256, 256>>>();
    qkv_gemm<<<dim3(3072 / 128, 4096 / 128), 256>>>(x, Wqkv);
    logits_kernel<<<dim3(32, 32, 32), 256>>>(score);
    softmax_kernel<<<BH * TSEQ, 256>>>(score);
    sv_kernel<<<dim3(1, 32, 32), 256>>>(score);
    outproj_gemm<<<dim3(1024 / 128, 4096 / 128), 256>>>(Wout, bout, out);
}

// round 5
// speedup vs baseline: 1.2850x; 1.2850x over previous
#include <cuda_runtime.h>
#include <cuda_bf16.h>
#include <math.h>
#include <stdint.h>

#define TSEQ   2048
#define DMODEL 1024
#define NH     16
#define HDIM   64
#define BATCH  2
#define BH     (BATCH*NH)   // 32

// ---------------- scratch (static device arrays; no allocation) ----------------
__device__ float g_F[(size_t)TSEQ * DMODEL];            // 8 MB  : F[d][dim] = PE(pos=d)
__device__ float g_Q[(size_t)BH * TSEQ * HDIM];         // 16 MB : [b,h,t,hd]
__device__ float g_Km[(size_t)BH * TSEQ * HDIM];        // 16 MB
__device__ float g_V[(size_t)BH * TSEQ * HDIM];         // 16 MB
__device__ float g_ctx[(size_t)BATCH * TSEQ * DMODEL];  // 16 MB
// bf16 split operands for tensor-core GEMMs (hi + lo, v = hi + lo)
__device__ __nv_bfloat16 g_Xhi[(size_t)4096 * 1024];
__device__ __nv_bfloat16 g_Xlo[(size_t)4096 * 1024];
__device__ __nv_bfloat16 g_WqkvT_hi[(size_t)3072 * 1024];
__device__ __nv_bfloat16 g_WqkvT_lo[(size_t)3072 * 1024];
__device__ __nv_bfloat16 g_WoutT_hi[(size_t)1024 * 1024];
__device__ __nv_bfloat16 g_WoutT_lo[(size_t)1024 * 1024];
__device__ __nv_bfloat16 g_Ctxhi[(size_t)4096 * 1024];
__device__ __nv_bfloat16 g_Ctxlo[(size_t)4096 * 1024];
// fallback scratch in case d_out does not include the score tensor
__device__ float g_scoreScratch[(size_t)BH * TSEQ * TSEQ];

// ---------------- 1) relative PE table: F[d][dim] ----------------
__global__ void pe_kernel() {
    int idx = blockIdx.x * 256 + threadIdx.x;
    int d   = idx >> 10;
    int dim = idx & (DMODEL - 1);
    int i2  = dim & ~1;
    float div = __expf(-9.210340371976184f * (float)i2 * (1.0f / (float)DMODEL));
    float ang = (float)d * div;
    g_F[idx] = (dim & 1) ? cosf(ang) : sinf(ang);
}

// ---------------- bf16 split: v = hi + lo ----------------
__global__ void split_kernel(const float* __restrict__ src,
                             __nv_bfloat16* __restrict__ hi,
                             __nv_bfloat16* __restrict__ lo) {
    int idx = blockIdx.x * 256 + threadIdx.x;
    float v = src[idx];
    __nv_bfloat16 h = __float2bfloat16(v);
    hi[idx] = h;
    lo[idx] = __float2bfloat16(v - __bfloat162float(h));
}

// ---------------- transpose + split: W[K=1024][C] -> T[C][1024] hi/lo ----------------
__global__ void transpose_split_kernel(const float* __restrict__ W,
                                       __nv_bfloat16* __restrict__ thi,
                                       __nv_bfloat16* __restrict__ tlo, int C) {
    __shared__ float tile[32][33];
    int c0 = blockIdx.x * 32, k0 = blockIdx.y * 32;
    int tx = threadIdx.x, ty = threadIdx.y;       // block (32, 8)
#pragma unroll
    for (int i = 0; i < 32; i += 8)
        tile[ty + i][tx] = W[(size_t)(k0 + ty + i) * C + c0 + tx];
    __syncthreads();
#pragma unroll
    for (int i = 0; i < 32; i += 8) {
        float v = tile[tx][ty + i];                       // W[k0+tx][c0+ty+i]
        size_t o = (size_t)(c0 + ty + i) * 1024 + k0 + tx;
        __nv_bfloat16 h = __float2bfloat16(v);
        thi[o] = h;
        tlo[o] = __float2bfloat16(v - __bfloat162float(h));
    }
}

// ================= mma.sync tensor-core GEMM (compiles for compute_100) =========
// C[token][feature] = X[token][k] * Wt[feature][k]
// bf16 split-3x: C = Ahi*Bhi + Ahi*Blo + Alo*Bhi  (fp32-accurate)
// Block tile 128x128, K-chunk 64, 8 warps each computing 64(m) x 32(n).

__device__ __forceinline__ void mma16816(float* c, const uint32_t* a,
                                         uint32_t b0, uint32_t b1) {
    asm volatile(
        "mma.sync.aligned.m16n8k16.row.col.f32.bf16.bf16.f32 "
        "{%0,%1,%2,%3}, {%4,%5,%6,%7}, {%8,%9}, {%0,%1,%2,%3};"
        : "+f"(c[0]), "+f"(c[1]), "+f"(c[2]), "+f"(c[3])
        : "r"(a[0]), "r"(a[1]), "r"(a[2]), "r"(a[3]), "r"(b0), "r"(b1));
}

#define SROW 72                // padded smem row length in bf16 (bank-conflict-free)
#define TILE_ELEMS (128 * SROW)

// load 128 rows x 64 bf16 (gmem row stride 1024) into smem rows of SROW
__device__ __forceinline__ void ld_tile(const __nv_bfloat16* __restrict__ src,
                                        __nv_bfloat16* __restrict__ dst, int tid) {
#pragma unroll
    for (int it = 0; it < 4; ++it) {
        int idx = tid + it * 256;      // 0..1023
        int r = idx >> 3;              // 0..127
        int c = idx & 7;               // 0..7 (chunks of 8 bf16 = 16B)
        uint4 v = *(const uint4*)(src + (size_t)r * 1024 + c * 8);
        *(uint4*)(dst + r * SROW + c * 8) = v;
    }
}

// MODE 0: qkv  (A = X, B = WqkvT; scatter into g_Q/g_Km/g_V)
// MODE 1: out  (A = ctx, B = WoutT; out = C + bias)
template <int MODE>
__global__ void __launch_bounds__(256, 1) gemm_mma(const float* __restrict__ bias,
                                                   float* __restrict__ outp) {
    extern __shared__ __nv_bfloat16 sm[];
    __nv_bfloat16* Ah = sm;
    __nv_bfloat16* Al = sm + TILE_ELEMS;
    __nv_bfloat16* Bh = sm + 2 * TILE_ELEMS;
    __nv_bfloat16* Bl = sm + 3 * TILE_ELEMS;

    const int tid = threadIdx.x;
    const int wid = tid >> 5, lane = tid & 31;
    const int g = lane >> 2, t = lane & 3;
    const int wm = wid & 1, wn = wid >> 1;      // warp tile: (wm*64, wn*32)
    const int bm = blockIdx.x;                  // token tile   (x128)
    const int bn = blockIdx.y;                  // feature tile (x128)

    const __nv_bfloat16* Agh = (MODE == 0 ? g_Xhi : g_Ctxhi) + (size_t)(bm * 128) * 1024;
    const __nv_bfloat16* Agl = (MODE == 0 ? g_Xlo : g_Ctxlo) + (size_t)(bm * 128) * 1024;
    const __nv_bfloat16* Bgh = (MODE == 0 ? g_WqkvT_hi : g_WoutT_hi) + (size_t)(bn * 128) * 1024;
    const __nv_bfloat16* Bgl = (MODE == 0 ? g_WqkvT_lo : g_WoutT_lo) + (size_t)(bn * 128) * 1024;

    float acc[4][4][4];
#pragma unroll
    for (int mi = 0; mi < 4; mi++)
#pragma unroll
        for (int ni = 0; ni < 4; ni++)
#pragma unroll
            for (int r = 0; r < 4; r++) acc[mi][ni][r] = 0.f;

    const uint32_t* Ah32 = (const uint32_t*)Ah;
    const uint32_t* Al32 = (const uint32_t*)Al;
    const uint32_t* Bh32 = (const uint32_t*)Bh;
    const uint32_t* Bl32 = (const uint32_t*)Bl;

    for (int kc = 0; kc < 16; kc++) {           // 16 chunks of K=64
        ld_tile(Agh + kc * 64, Ah, tid);
        ld_tile(Agl + kc * 64, Al, tid);
        ld_tile(Bgh + kc * 64, Bh, tid);
        ld_tile(Bgl + kc * 64, Bl, tid);
        __syncthreads();

#pragma unroll
        for (int ks = 0; ks < 4; ks++) {        // 4 k16 steps
            // A fragments (hi & lo) for 4 m-frags
            uint32_t ah[4][4], al[4][4];
#pragma unroll
            for (int mi = 0; mi < 4; mi++) {
                int rb = wm * 64 + mi * 16 + g;              // fragment row
                int o0 = rb * 36 + ks * 8 + t;               // b32 index (SROW/2=36)
                int o1 = (rb + 8) * 36 + ks * 8 + t;
                ah[mi][0] = Ah32[o0];     ah[mi][1] = Ah32[o1];
                ah[mi][2] = Ah32[o0 + 4]; ah[mi][3] = Ah32[o1 + 4];
                al[mi][0] = Al32[o0];     al[mi][1] = Al32[o1];
                al[mi][2] = Al32[o0 + 4]; al[mi][3] = Al32[o1 + 4];
            }
#pragma unroll
            for (int ni = 0; ni < 4; ni++) {
                int nb = wn * 32 + ni * 8 + g;               // B fragment col (n)
                int o = nb * 36 + ks * 8 + t;
                uint32_t bh0 = Bh32[o], bh1 = Bh32[o + 4];
                uint32_t bl0 = Bl32[o], bl1 = Bl32[o + 4];
#pragma unroll
                for (int mi = 0; mi < 4; mi++) {
                    mma16816(acc[mi][ni], ah[mi], bh0, bh1);
                    mma16816(acc[mi][ni], ah[mi], bl0, bl1);
                    mma16816(acc[mi][ni], al[mi], bh0, bh1);
                }
            }
        }
        __syncthreads();
    }

    // ---------------- epilogue ----------------
#pragma unroll
    for (int mi = 0; mi < 4; mi++) {
        int m0 = bm * 128 + wm * 64 + mi * 16 + g;   // token row (and +8)
#pragma unroll
        for (int ni = 0; ni < 4; ni++) {
            int n = bn * 128 + wn * 32 + ni * 8 + 2 * t;   // feature col (even)
            if (MODE == 0) {
                int sect = n >> 10, h = (n >> 6) & (NH - 1), hd = n & 63;
                float* dst = (sect == 0) ? g_Q : ((sect == 1) ? g_Km : g_V);
                int b0 = m0 >> 11, t0 = m0 & (TSEQ - 1);
                *(float2*)&dst[(((size_t)b0 * NH + h) * TSEQ + t0) * HDIM + hd] =
                    make_float2(acc[mi][ni][0], acc[mi][ni][1]);
                int m1 = m0 + 8;
                int b1 = m1 >> 11, t1 = m1 & (TSEQ - 1);
                *(float2*)&dst[(((size_t)b1 * NH + h) * TSEQ + t1) * HDIM + hd] =
                    make_float2(acc[mi][ni][2], acc[mi][ni][3]);
            } else {
                float2 bb = *(const float2*)&bias[n];
                *(float2*)&outp[(size_t)m0 * 1024 + n] =
                    make_float2(acc[mi][ni][0] + bb.x, acc[mi][ni][1] + bb.y);
                *(float2*)&outp[(size_t)(m0 + 8) * 1024 + n] =
                    make_float2(acc[mi][ni][2] + bb.x, acc[mi][ni][3] + bb.y);
            }
        }
    }
}

// ---------------- 3) fused causal logits: (Q.K^T + Q.F[q-k]) / 8 ----------------
__global__ void __launch_bounds__(256) logits_kernel(float* __restrict__ score) {
    int bn = blockIdx.x;      // k tile
    int bm = blockIdx.y;      // q tile
    if (bn > bm) return;      // fully masked tile
    int z = blockIdx.z;       // b*H + h
    int h = z & (NH - 1);

    __shared__ float Qs[32][64];
    __shared__ float Ks[32][64];
    __shared__ float Fs[32][128];

    int tid = threadIdx.x;
    int tx = tid & 15, ty = tid >> 4;

    float acc[4][4];
#pragma unroll
    for (int i = 0; i < 4; i++)
#pragma unroll
        for (int j = 0; j < 4; j++) acc[i][j] = 0.f;

    const float* Qg = &g_Q[((size_t)z * TSEQ + bm * 64) * HDIM];
    const float* Kg = &g_Km[((size_t)z * TSEQ + bn * 64) * HDIM];
    int dtile = (bm - bn) * 64;
    int r0 = 4 * (ty - tx) + 60;

    for (int half = 0; half < 2; half++) {
        int hoff = half * 32;
#pragma unroll
        for (int it = 0; it < 2; it++) {
            int idx = tid + it * 256;
            int r = idx >> 3;
            int c4 = idx & 7;
            float4 q4 = *(const float4*)&Qg[(size_t)r * HDIM + hoff + c4 * 4];
            Qs[c4 * 4 + 0][r] = q4.x; Qs[c4 * 4 + 1][r] = q4.y;
            Qs[c4 * 4 + 2][r] = q4.z; Qs[c4 * 4 + 3][r] = q4.w;
            float4 k4 = *(const float4*)&Kg[(size_t)r * HDIM + hoff + c4 * 4];
            Ks[c4 * 4 + 0][r] = k4.x; Ks[c4 * 4 + 1][r] = k4.y;
            Ks[c4 * 4 + 2][r] = k4.z; Ks[c4 * 4 + 3][r] = k4.w;
        }
        for (int idx = tid; idx < 127 * 8; idx += 256) {
            int r = idx >> 3;
            int c4 = idx & 7;
            int d = dtile - 63 + r;
            float4 f4 = make_float4(0.f, 0.f, 0.f, 0.f);
            if (d >= 0 && d < TSEQ)
                f4 = *(const float4*)&g_F[(size_t)d * DMODEL + h * HDIM + hoff + c4 * 4];
            Fs[c4 * 4 + 0][r] = f4.x; Fs[c4 * 4 + 1][r] = f4.y;
            Fs[c4 * 4 + 2][r] = f4.z; Fs[c4 * 4 + 3][r] = f4.w;
        }
        __syncthreads();

#pragma unroll
        for (int hc = 0; hc < 32; hc++) {
            float4 av = *(float4*)&Qs[hc][ty * 4];
            float4 bv = *(float4*)&Ks[hc][tx * 4];
            float4 f0 = *(float4*)&Fs[hc][r0];
            float4 f1 = *(float4*)&Fs[hc][r0 + 4];
            float a[4]  = {av.x, av.y, av.z, av.w};
            float b4[4] = {bv.x, bv.y, bv.z, bv.w};
            float fv[7] = {f0.x, f0.y, f0.z, f0.w, f1.x, f1.y, f1.z};
#pragma unroll
            for (int i = 0; i < 4; i++)
#pragma unroll
                for (int j = 0; j < 4; j++) {
                    acc[i][j] = fmaf(a[i], b4[j], acc[i][j]);
                    acc[i][j] = fmaf(a[i], fv[i - j + 3], acc[i][j]);
                }
        }
        __syncthreads();
    }

    const float inv_scale = 0.125f;
    size_t base = ((size_t)z * TSEQ + bm * 64 + ty * 4) * TSEQ + bn * 64 + tx * 4;
#pragma unroll
    for (int i = 0; i < 4; i++) {
        *(float4*)&score[base + (size_t)i * TSEQ] =
            make_float4(acc[i][0] * inv_scale, acc[i][1] * inv_scale,
                        acc[i][2] * inv_scale, acc[i][3] * inv_scale);
    }
}

// ---------------- 4) causal row softmax, in-place on score ----------------
__global__ void __launch_bounds__(256) softmax_kernel(float* __restrict__ score) {
    size_t row = blockIdx.x;
    int q = (int)(row & (TSEQ - 1));
    float* p = &score[row * TSEQ];
    int tid = threadIdx.x;

    __shared__ float red[8];
    float v[8];
    float mx = -1e30f;
#pragma unroll
    for (int i = 0; i < 8; i++) {
        int k = i * 256 + tid;
        v[i] = (k <= q) ? p[k] : -1e30f;
        mx = fmaxf(mx, v[i]);
    }
#pragma unroll
    for (int o = 16; o > 0; o >>= 1) mx = fmaxf(mx, __shfl_xor_sync(0xffffffffu, mx, o));
    if ((tid & 31) == 0) red[tid >> 5] = mx;
    __syncthreads();
    float bmx = red[0];
#pragma unroll
    for (int w = 1; w < 8; w++) bmx = fmaxf(bmx, red[w]);

    float s = 0.f;
#pragma unroll
    for (int i = 0; i < 8; i++) {
        int k = i * 256 + tid;
        float e = (k <= q) ? __expf(v[i] - bmx) : 0.f;
        v[i] = e;
        s += e;
    }
#pragma unroll
    for (int o = 16; o > 0; o >>= 1) s += __shfl_xor_sync(0xffffffffu, s, o);
    __syncthreads();
    if ((tid & 31) == 0) red[tid >> 5] = s;
    __syncthreads();
    float tot = 0.f;
#pragma unroll
    for (int w = 0; w < 8; w++) tot += red[w];
    float inv = 1.0f / tot;
#pragma unroll
    for (int i = 0; i < 8; i++) {
        int k = i * 256 + tid;
        p[k] = v[i] * inv;
    }
}

// ---------------- 5) ctx = S @ V (causal) ----------------
__global__ void __launch_bounds__(256) sv_kernel(const float* __restrict__ score) {
    int bm = blockIdx.y;
    int z = blockIdx.z;
    int b = z >> 4, h = z & (NH - 1);

    __shared__ float Ss[64][68];
    __shared__ float Vs[64][68];
    int tid = threadIdx.x;
    int tx = tid & 15, ty = tid >> 4;

    float acc[4][4];
#pragma unroll
    for (int i = 0; i < 4; i++)
#pragma unroll
        for (int j = 0; j < 4; j++) acc[i][j] = 0.f;

    const float* Sg = &score[((size_t)z * TSEQ + bm * 64) * TSEQ];
    const float* Vg = &g_V[(size_t)z * TSEQ * HDIM];

    for (int kt = 0; kt <= bm; kt++) {
#pragma unroll
        for (int it = 0; it < 4; it++) {
            int idx = tid + it * 256;
            int r = idx >> 4;
            int c4 = idx & 15;
            *(float4*)&Ss[r][c4 * 4] =
                *(const float4*)&Sg[(size_t)r * TSEQ + kt * 64 + c4 * 4];
            *(float4*)&Vs[r][c4 * 4] =
                *(const float4*)&Vg[(size_t)(kt * 64 + r) * HDIM + c4 * 4];
        }
        __syncthreads();
#pragma unroll
        for (int kk = 0; kk < 64; kk++) {
            float a[4];
#pragma unroll
            for (int i = 0; i < 4; i++) a[i] = Ss[ty * 4 + i][kk];
            float4 bv = *(float4*)&Vs[kk][tx * 4];
            float b4[4] = {bv.x, bv.y, bv.z, bv.w};
#pragma unroll
            for (int i = 0; i < 4; i++)
#pragma unroll
                for (int j = 0; j < 4; j++) acc[i][j] = fmaf(a[i], b4[j], acc[i][j]);
        }
        __syncthreads();
    }
#pragma unroll
    for (int i = 0; i < 4; i++) {
        int t = bm * 64 + ty * 4 + i;
        *(float4*)&g_ctx[((size_t)b * TSEQ + t) * DMODEL + h * HDIM + tx * 4] =
            make_float4(acc[i][0], acc[i][1], acc[i][2], acc[i][3]);
    }
}

// ---------------- launch ----------------
extern "C" void kernel_launch(void* const* d_in, const int* in_sizes, int n_in,
                              void* d_out, int out_size) {
    const float* x    = (const float*)d_in[0];   // [B,T,D]
    const float* Wqkv = (const float*)d_in[2];   // [D,3D]
    const float* Wout = (const float*)d_in[3];   // [D,D]
    const float* bout = (const float*)d_in[4];   // [D]

    float* out = (float*)d_out;
    const size_t outElems = (size_t)BATCH * TSEQ * DMODEL;
    const size_t scoreElems = (size_t)BH * TSEQ * TSEQ;
    float* score = ((size_t)out_size >= outElems + scoreElems)
                       ? (out + outElems)
                       : g_scoreScratch;

    const int GEMM_SMEM = 4 * TILE_ELEMS * (int)sizeof(__nv_bfloat16);   // 73728 B
    cudaFuncSetAttribute(gemm_mma<0>,
                         cudaFuncAttributeMaxDynamicSharedMemorySize, GEMM_SMEM);
    cudaFuncSetAttribute(gemm_mma<1>,
                         cudaFuncAttributeMaxDynamicSharedMemorySize, GEMM_SMEM);

    // device-global pointers for split kernels
    float* ctxp;   cudaGetSymbolAddress((void**)&ctxp, g_ctx);
    __nv_bfloat16 *xhi, *xlo, *cth, *ctl, *wqh, *wql, *woh, *wol;
    cudaGetSymbolAddress((void**)&xhi, g_Xhi);
    cudaGetSymbolAddress((void**)&xlo, g_Xlo);
    cudaGetSymbolAddress((void**)&cth, g_Ctxhi);
    cudaGetSymbolAddress((void**)&ctl, g_Ctxlo);
    cudaGetSymbolAddress((void**)&wqh, g_WqkvT_hi);
    cudaGetSymbolAddress((void**)&wql, g_WqkvT_lo);
    cudaGetSymbolAddress((void**)&woh, g_WoutT_hi);
    cudaGetSymbolAddress((void**)&wol, g_WoutT_lo);

    pe_kernel<<<(TSEQ * DMODEL) / 256, 256>>>();
    split_kernel<<<(4096 * 1024) / 256, 256>>>(x, xhi, xlo);
    transpose_split_kernel<<<dim3(3072 / 32, 1024 / 32), dim3(32, 8)>>>(Wqkv, wqh, wql, 3072);
    transpose_split_kernel<<<dim3(1024 / 32, 1024 / 32), dim3(32, 8)>>>(Wout, woh, wol, 1024);

    gemm_mma<0><<<dim3(32, 24), 256, GEMM_SMEM>>>(nullptr, nullptr);   // QKV

    logits_kernel<<<dim3(32, 32, 32), 256>>>(score);
    softmax_kernel<<<BH * TSEQ, 256>>>(score);
    sv_kernel<<<dim3(1, 32, 32), 256>>>(score);

    split_kernel<<<(4096 * 1024) / 256, 256>>>(ctxp, cth, ctl);
    gemm_mma<1><<<dim3(32, 8), 256, GEMM_SMEM>>>(bout, out);           // out proj
}

// round 6
// speedup vs baseline: 1.6649x; 1.2957x over previous
#include <cuda_runtime.h>
#include <cuda_bf16.h>
#include <math.h>
#include <stdint.h>

#define TSEQ   2048
#define DMODEL 1024
#define NH     16
#define HDIM   64
#define BATCH  2
#define BH     (BATCH*NH)   // 32

// ---------------- scratch (static device arrays; no allocation) ----------------
__device__ float g_V[(size_t)BH * TSEQ * HDIM];         // 16 MB  [z][t][hd] fp32
__device__ float g_W[(size_t)BH * TSEQ * TSEQ];         // 512 MB [z][q][l] skew gemm
// bf16 hi/lo operands
__device__ __nv_bfloat16 g_Qhi[(size_t)BH * TSEQ * HDIM];   // [z][t][hd]
__device__ __nv_bfloat16 g_Qlo[(size_t)BH * TSEQ * HDIM];
__device__ __nv_bfloat16 g_Khi[(size_t)BH * TSEQ * HDIM];
__device__ __nv_bfloat16 g_Klo[(size_t)BH * TSEQ * HDIM];
__device__ __nv_bfloat16 g_Ehi[(size_t)TSEQ * DMODEL];      // E[l][dim] (pos = 2047-l)
__device__ __nv_bfloat16 g_Elo[(size_t)TSEQ * DMODEL];
__device__ __nv_bfloat16 g_Xhi[(size_t)4096 * 1024];
__device__ __nv_bfloat16 g_Xlo[(size_t)4096 * 1024];
__device__ __nv_bfloat16 g_WqkvT_hi[(size_t)3072 * 1024];
__device__ __nv_bfloat16 g_WqkvT_lo[(size_t)3072 * 1024];
__device__ __nv_bfloat16 g_WoutT_hi[(size_t)1024 * 1024];
__device__ __nv_bfloat16 g_WoutT_lo[(size_t)1024 * 1024];
__device__ __nv_bfloat16 g_Ctxhi[(size_t)4096 * 1024];
__device__ __nv_bfloat16 g_Ctxlo[(size_t)4096 * 1024];
// fallback scratch in case d_out does not include the score tensor
__device__ float g_scoreScratch[(size_t)BH * TSEQ * TSEQ];

// ---------------- helpers ----------------
__device__ __forceinline__ uint32_t pack2(__nv_bfloat16 a, __nv_bfloat16 b) {
    uint16_t x = *(uint16_t*)&a, y = *(uint16_t*)&b;
    return (uint32_t)x | ((uint32_t)y << 16);
}
__device__ __forceinline__ void mma16816(float* c, const uint32_t* a,
                                         uint32_t b0, uint32_t b1) {
    asm volatile(
        "mma.sync.aligned.m16n8k16.row.col.f32.bf16.bf16.f32 "
        "{%0,%1,%2,%3}, {%4,%5,%6,%7}, {%8,%9}, {%0,%1,%2,%3};"
        : "+f"(c[0]), "+f"(c[1]), "+f"(c[2]), "+f"(c[3])
        : "r"(a[0]), "r"(a[1]), "r"(a[2]), "r"(a[3]), "r"(b0), "r"(b1));
}

// ---------------- 1) relative PE table as bf16 hi/lo (E layout: row l, pos=2047-l) ----
__global__ void pe_kernel() {
    int idx = blockIdx.x * 256 + threadIdx.x;
    int l   = idx >> 10;
    int dim = idx & (DMODEL - 1);
    int pos = (TSEQ - 1) - l;
    int i2  = dim & ~1;
    float div = __expf(-9.210340371976184f * (float)i2 * (1.0f / (float)DMODEL));
    float ang = (float)pos * div;
    float v = (dim & 1) ? cosf(ang) : sinf(ang);
    __nv_bfloat16 h = __float2bfloat16(v);
    g_Ehi[idx] = h;
    g_Elo[idx] = __float2bfloat16(v - __bfloat162float(h));
}

// ---------------- bf16 split: v = hi + lo ----------------
__global__ void split_kernel(const float* __restrict__ src,
                             __nv_bfloat16* __restrict__ hi,
                             __nv_bfloat16* __restrict__ lo) {
    int idx = blockIdx.x * 256 + threadIdx.x;
    float v = src[idx];
    __nv_bfloat16 h = __float2bfloat16(v);
    hi[idx] = h;
    lo[idx] = __float2bfloat16(v - __bfloat162float(h));
}

// ---------------- transpose + split: W[K=1024][C] -> T[C][1024] hi/lo ----------------
__global__ void transpose_split_kernel(const float* __restrict__ W,
                                       __nv_bfloat16* __restrict__ thi,
                                       __nv_bfloat16* __restrict__ tlo, int C) {
    __shared__ float tile[32][33];
    int c0 = blockIdx.x * 32, k0 = blockIdx.y * 32;
    int tx = threadIdx.x, ty = threadIdx.y;       // block (32, 8)
#pragma unroll
    for (int i = 0; i < 32; i += 8)
        tile[ty + i][tx] = W[(size_t)(k0 + ty + i) * C + c0 + tx];
    __syncthreads();
#pragma unroll
    for (int i = 0; i < 32; i += 8) {
        float v = tile[tx][ty + i];
        size_t o = (size_t)(c0 + ty + i) * 1024 + k0 + tx;
        __nv_bfloat16 h = __float2bfloat16(v);
        thi[o] = h;
        tlo[o] = __float2bfloat16(v - __bfloat162float(h));
    }
}

// ================= big GEMMs (qkv / outproj), R5-proven =================
#define SROW 72                // padded smem row (64 data + 8), stride32 = 36
#define TILE_ELEMS (128 * SROW)

__device__ __forceinline__ void ld_tile(const __nv_bfloat16* __restrict__ src,
                                        size_t stride,
                                        __nv_bfloat16* __restrict__ dst, int tid) {
#pragma unroll
    for (int it = 0; it < 4; ++it) {
        int idx = tid + it * 256;      // 0..1023
        int r = idx >> 3;              // 0..127
        int c = idx & 7;               // 0..7 (16B chunks)
        uint4 v = *(const uint4*)(src + (size_t)r * stride + c * 8);
        *(uint4*)(dst + r * SROW + c * 8) = v;
    }
}

// MODE 0: qkv  (A = X, B = WqkvT; emit Qhi/lo, Khi/lo bf16 + V fp32)
// MODE 1: out  (A = Ctx hi/lo, B = WoutT; out = C + bias)
template <int MODE>
__global__ void __launch_bounds__(256, 1) gemm_mma(const float* __restrict__ bias,
                                                   float* __restrict__ outp) {
    extern __shared__ __nv_bfloat16 sm[];
    __nv_bfloat16* Ah = sm;
    __nv_bfloat16* Al = sm + TILE_ELEMS;
    __nv_bfloat16* Bh = sm + 2 * TILE_ELEMS;
    __nv_bfloat16* Bl = sm + 3 * TILE_ELEMS;

    const int tid = threadIdx.x;
    const int wid = tid >> 5, lane = tid & 31;
    const int g = lane >> 2, t = lane & 3;
    const int wm = wid & 1, wn = wid >> 1;
    const int bm = blockIdx.x;                  // token tile   (x128)
    const int bn = blockIdx.y;                  // feature tile (x128)

    const __nv_bfloat16* Agh = (MODE == 0 ? g_Xhi : g_Ctxhi) + (size_t)(bm * 128) * 1024;
    const __nv_bfloat16* Agl = (MODE == 0 ? g_Xlo : g_Ctxlo) + (size_t)(bm * 128) * 1024;
    const __nv_bfloat16* Bgh = (MODE == 0 ? g_WqkvT_hi : g_WoutT_hi) + (size_t)(bn * 128) * 1024;
    const __nv_bfloat16* Bgl = (MODE == 0 ? g_WqkvT_lo : g_WoutT_lo) + (size_t)(bn * 128) * 1024;

    float acc[4][4][4];
#pragma unroll
    for (int mi = 0; mi < 4; mi++)
#pragma unroll
        for (int ni = 0; ni < 4; ni++)
#pragma unroll
            for (int r = 0; r < 4; r++) acc[mi][ni][r] = 0.f;

    const uint32_t* Ah32 = (const uint32_t*)Ah;
    const uint32_t* Al32 = (const uint32_t*)Al;
    const uint32_t* Bh32 = (const uint32_t*)Bh;
    const uint32_t* Bl32 = (const uint32_t*)Bl;

    for (int kc = 0; kc < 16; kc++) {
        ld_tile(Agh + kc * 64, 1024, Ah, tid);
        ld_tile(Agl + kc * 64, 1024, Al, tid);
        ld_tile(Bgh + kc * 64, 1024, Bh, tid);
        ld_tile(Bgl + kc * 64, 1024, Bl, tid);
        __syncthreads();

#pragma unroll
        for (int ks = 0; ks < 4; ks++) {
            uint32_t ah[4][4], al[4][4];
#pragma unroll
            for (int mi = 0; mi < 4; mi++) {
                int rb = wm * 64 + mi * 16 + g;
                int o0 = rb * 36 + ks * 8 + t;
                int o1 = (rb + 8) * 36 + ks * 8 + t;
                ah[mi][0] = Ah32[o0];     ah[mi][1] = Ah32[o1];
                ah[mi][2] = Ah32[o0 + 4]; ah[mi][3] = Ah32[o1 + 4];
                al[mi][0] = Al32[o0];     al[mi][1] = Al32[o1];
                al[mi][2] = Al32[o0 + 4]; al[mi][3] = Al32[o1 + 4];
            }
#pragma unroll
            for (int ni = 0; ni < 4; ni++) {
                int nb = wn * 32 + ni * 8 + g;
                int o = nb * 36 + ks * 8 + t;
                uint32_t bh0 = Bh32[o], bh1 = Bh32[o + 4];
                uint32_t bl0 = Bl32[o], bl1 = Bl32[o + 4];
#pragma unroll
                for (int mi = 0; mi < 4; mi++) {
                    mma16816(acc[mi][ni], ah[mi], bh0, bh1);
                    mma16816(acc[mi][ni], ah[mi], bl0, bl1);
                    mma16816(acc[mi][ni], al[mi], bh0, bh1);
                }
            }
        }
        __syncthreads();
    }

    // ---------------- epilogue ----------------
#pragma unroll
    for (int mi = 0; mi < 4; mi++) {
        int m0 = bm * 128 + wm * 64 + mi * 16 + g;
#pragma unroll
        for (int ni = 0; ni < 4; ni++) {
            int n = bn * 128 + wn * 32 + ni * 8 + 2 * t;   // feature col (even)
            float c0 = acc[mi][ni][0], c1 = acc[mi][ni][1];
            float c2 = acc[mi][ni][2], c3 = acc[mi][ni][3];
            if (MODE == 0) {
                int sect = n >> 10, h = (n >> 6) & (NH - 1), hd = n & 63;
                int b0 = m0 >> 11, t0 = m0 & (TSEQ - 1);
                int m1 = m0 + 8, b1 = m1 >> 11, t1 = m1 & (TSEQ - 1);
                size_t i0 = (((size_t)b0 * NH + h) * TSEQ + t0) * HDIM + hd;
                size_t i1 = (((size_t)b1 * NH + h) * TSEQ + t1) * HDIM + hd;
                if (sect == 2) {
                    *(float2*)&g_V[i0] = make_float2(c0, c1);
                    *(float2*)&g_V[i1] = make_float2(c2, c3);
                } else {
                    __nv_bfloat16* Dh = sect ? g_Khi : g_Qhi;
                    __nv_bfloat16* Dl = sect ? g_Klo : g_Qlo;
                    __nv_bfloat16 h0 = __float2bfloat16(c0), h1 = __float2bfloat16(c1);
                    __nv_bfloat16 h2 = __float2bfloat16(c2), h3 = __float2bfloat16(c3);
                    *(uint32_t*)&Dh[i0] = pack2(h0, h1);
                    *(uint32_t*)&Dl[i0] = pack2(
                        __float2bfloat16(c0 - __bfloat162float(h0)),
                        __float2bfloat16(c1 - __bfloat162float(h1)));
                    *(uint32_t*)&Dh[i1] = pack2(h2, h3);
                    *(uint32_t*)&Dl[i1] = pack2(
                        __float2bfloat16(c2 - __bfloat162float(h2)),
                        __float2bfloat16(c3 - __bfloat162float(h3)));
                }
            } else {
                float2 bb = *(const float2*)&bias[n];
                *(float2*)&outp[(size_t)m0 * 1024 + n] = make_float2(c0 + bb.x, c1 + bb.y);
                *(float2*)&outp[(size_t)(m0 + 8) * 1024 + n] = make_float2(c2 + bb.x, c3 + bb.y);
            }
        }
    }
}

// ================= shared single-chunk (K=64) mma core for W & logits =============
// acc[4][4][4] += split3( A(128x64) @ B(128x64)^T ), operands already in smem.
__device__ __forceinline__ void mma_k64(float acc[4][4][4],
                                        const uint32_t* Ah32, const uint32_t* Al32,
                                        const uint32_t* Bh32, const uint32_t* Bl32,
                                        int wm, int wn, int g, int t) {
#pragma unroll
    for (int ks = 0; ks < 4; ks++) {
        uint32_t ah[4][4], al[4][4];
#pragma unroll
        for (int mi = 0; mi < 4; mi++) {
            int rb = wm * 64 + mi * 16 + g;
            int o0 = rb * 36 + ks * 8 + t;
            int o1 = (rb + 8) * 36 + ks * 8 + t;
            ah[mi][0] = Ah32[o0];     ah[mi][1] = Ah32[o1];
            ah[mi][2] = Ah32[o0 + 4]; ah[mi][3] = Ah32[o1 + 4];
            al[mi][0] = Al32[o0];     al[mi][1] = Al32[o1];
            al[mi][2] = Al32[o0 + 4]; al[mi][3] = Al32[o1 + 4];
        }
#pragma unroll
        for (int ni = 0; ni < 4; ni++) {
            int nb = wn * 32 + ni * 8 + g;
            int o = nb * 36 + ks * 8 + t;
            uint32_t bh0 = Bh32[o], bh1 = Bh32[o + 4];
            uint32_t bl0 = Bl32[o], bl1 = Bl32[o + 4];
#pragma unroll
            for (int mi = 0; mi < 4; mi++) {
                mma16816(acc[mi][ni], ah[mi], bh0, bh1);
                mma16816(acc[mi][ni], ah[mi], bl0, bl1);
                mma16816(acc[mi][ni], al[mi], bh0, bh1);
            }
        }
    }
}

// ---------------- W = Q @ E^T per head (skew GEMM), needed tiles only ------------
__global__ void __launch_bounds__(256, 1) w_mma() {
    const int ln = blockIdx.x;     // l tile
    const int bm = blockIdx.y;     // q tile
    if (ln < 15 - bm) return;      // unneeded tile
    const int z = blockIdx.z;
    const int h = z & (NH - 1);

    extern __shared__ __nv_bfloat16 smw[];
    __nv_bfloat16* Qh = smw;
    __nv_bfloat16* Ql = smw + TILE_ELEMS;
    __nv_bfloat16* Ehs = smw + 2 * TILE_ELEMS;
    __nv_bfloat16* Els = smw + 3 * TILE_ELEMS;

    const int tid = threadIdx.x;
    const int wid = tid >> 5, lane = tid & 31;
    const int g = lane >> 2, t = lane & 3;
    const int wm = wid & 1, wn = wid >> 1;

    ld_tile(g_Qhi + ((size_t)z * TSEQ + bm * 128) * HDIM, 64, Qh, tid);
    ld_tile(g_Qlo + ((size_t)z * TSEQ + bm * 128) * HDIM, 64, Ql, tid);
    ld_tile(g_Ehi + (size_t)(ln * 128) * DMODEL + h * HDIM, 1024, Ehs, tid);
    ld_tile(g_Elo + (size_t)(ln * 128) * DMODEL + h * HDIM, 1024, Els, tid);
    __syncthreads();

    float acc[4][4][4];
#pragma unroll
    for (int mi = 0; mi < 4; mi++)
#pragma unroll
        for (int ni = 0; ni < 4; ni++)
#pragma unroll
            for (int r = 0; r < 4; r++) acc[mi][ni][r] = 0.f;

    mma_k64(acc, (const uint32_t*)Qh, (const uint32_t*)Ql,
            (const uint32_t*)Ehs, (const uint32_t*)Els, wm, wn, g, t);

    float* Wz = g_W + (size_t)z * TSEQ * TSEQ;
#pragma unroll
    for (int mi = 0; mi < 4; mi++) {
        int q0 = bm * 128 + wm * 64 + mi * 16 + g;
#pragma unroll
        for (int ni = 0; ni < 4; ni++) {
            int l = ln * 128 + wn * 32 + ni * 8 + 2 * t;
            *(float2*)&Wz[(size_t)q0 * TSEQ + l] =
                make_float2(acc[mi][ni][0], acc[mi][ni][1]);
            *(float2*)&Wz[(size_t)(q0 + 8) * TSEQ + l] =
                make_float2(acc[mi][ni][2], acc[mi][ni][3]);
        }
    }
}

// ---------------- logits = (Q@K^T + gather(W)) / 8, causal tiles -----------------
__global__ void __launch_bounds__(256, 1) logits_mma(float* __restrict__ score) {
    const int bn = blockIdx.x;     // k tile
    const int bm = blockIdx.y;     // q tile
    if (bn > bm) return;
    const int z = blockIdx.z;

    extern __shared__ __nv_bfloat16 sml[];
    __nv_bfloat16* Qh = sml;
    __nv_bfloat16* Ql = sml + TILE_ELEMS;
    __nv_bfloat16* Kh = sml + 2 * TILE_ELEMS;
    __nv_bfloat16* Kl = sml + 3 * TILE_ELEMS;

    const int tid = threadIdx.x;
    const int wid = tid >> 5, lane = tid & 31;
    const int g = lane >> 2, t = lane & 3;
    const int wm = wid & 1, wn = wid >> 1;

    ld_tile(g_Qhi + ((size_t)z * TSEQ + bm * 128) * HDIM, 64, Qh, tid);
    ld_tile(g_Qlo + ((size_t)z * TSEQ + bm * 128) * HDIM, 64, Ql, tid);
    ld_tile(g_Khi + ((size_t)z * TSEQ + bn * 128) * HDIM, 64, Kh, tid);
    ld_tile(g_Klo + ((size_t)z * TSEQ + bn * 128) * HDIM, 64, Kl, tid);
    __syncthreads();

    float acc[4][4][4];
#pragma unroll
    for (int mi = 0; mi < 4; mi++)
#pragma unroll
        for (int ni = 0; ni < 4; ni++)
#pragma unroll
            for (int r = 0; r < 4; r++) acc[mi][ni][r] = 0.f;

    mma_k64(acc, (const uint32_t*)Qh, (const uint32_t*)Ql,
            (const uint32_t*)Kh, (const uint32_t*)Kl, wm, wn, g, t);

    const float* Wz = g_W + (size_t)z * TSEQ * TSEQ;
    const float inv_scale = 0.125f;
#pragma unroll
    for (int mi = 0; mi < 4; mi++) {
        int q0 = bm * 128 + wm * 64 + mi * 16 + g;
        int q1 = q0 + 8;
#pragma unroll
        for (int ni = 0; ni < 4; ni++) {
            int k0 = bn * 128 + wn * 32 + ni * 8 + 2 * t;
            // att_e[q][k] = W[q][2047 - q + k]  (masked cols read garbage; softmax zeroes)
            float e0 = Wz[(size_t)q0 * TSEQ + (2047 - q0 + k0)];
            float e1 = Wz[(size_t)q0 * TSEQ + (2047 - q0 + k0 + 1)];
            float e2 = Wz[(size_t)q1 * TSEQ + (2047 - q1 + k0)];
            float e3 = Wz[(size_t)q1 * TSEQ + (2047 - q1 + k0 + 1)];
            *(float2*)&score[((size_t)z * TSEQ + q0) * TSEQ + k0] =
                make_float2((acc[mi][ni][0] + e0) * inv_scale,
                            (acc[mi][ni][1] + e1) * inv_scale);
            *(float2*)&score[((size_t)z * TSEQ + q1) * TSEQ + k0] =
                make_float2((acc[mi][ni][2] + e2) * inv_scale,
                            (acc[mi][ni][3] + e3) * inv_scale);
        }
    }
}

// ---------------- causal row softmax, in-place; zeros for k>q ----------------
__global__ void __launch_bounds__(256) softmax_kernel(float* __restrict__ score) {
    size_t row = blockIdx.x;
    int q = (int)(row & (TSEQ - 1));
    float* p = &score[row * TSEQ];
    int tid = threadIdx.x;

    __shared__ float red[8];
    float v[8];
    float mx = -1e30f;
#pragma unroll
    for (int i = 0; i < 8; i++) {
        int k = i * 256 + tid;
        v[i] = (k <= q) ? p[k] : -1e30f;
        mx = fmaxf(mx, v[i]);
    }
#pragma unroll
    for (int o = 16; o > 0; o >>= 1) mx = fmaxf(mx, __shfl_xor_sync(0xffffffffu, mx, o));
    if ((tid & 31) == 0) red[tid >> 5] = mx;
    __syncthreads();
    float bmx = red[0];
#pragma unroll
    for (int w = 1; w < 8; w++) bmx = fmaxf(bmx, red[w]);

    float s = 0.f;
#pragma unroll
    for (int i = 0; i < 8; i++) {
        int k = i * 256 + tid;
        float e = (k <= q) ? __expf(v[i] - bmx) : 0.f;
        v[i] = e;
        s += e;
    }
#pragma unroll
    for (int o = 16; o > 0; o >>= 1) s += __shfl_xor_sync(0xffffffffu, s, o);
    __syncthreads();
    if ((tid & 31) == 0) red[tid >> 5] = s;
    __syncthreads();
    float tot = 0.f;
#pragma unroll
    for (int w = 0; w < 8; w++) tot += red[w];
    float inv = 1.0f / tot;
#pragma unroll
    for (int i = 0; i < 8; i++) {
        int k = i * 256 + tid;
        p[k] = v[i] * inv;
    }
}

// ---------------- ctx = S @ V via mma (in-kernel fp32->bf16 split) ---------------
// per CTA: q tile 128 x full hd 64, loop causal k chunks of 128.
#define SROW2 136               // 128 data + 8 pad; stride32 = 68
__global__ void __launch_bounds__(256, 1) sv_mma(const float* __restrict__ score) {
    const int bm = blockIdx.x;     // q tile
    const int z  = blockIdx.y;
    const int b  = z >> 4, h = z & (NH - 1);

    extern __shared__ __nv_bfloat16 smv[];
    __nv_bfloat16* Sh = smv;                       // [128][136]
    __nv_bfloat16* Sl = smv + 128 * SROW2;
    __nv_bfloat16* Vh = smv + 2 * 128 * SROW2;     // [64][136] (transposed: [hd][k])
    __nv_bfloat16* Vl = Vh + 64 * SROW2;

    const int tid = threadIdx.x;
    const int wid = tid >> 5, lane = tid & 31;
    const int g = lane >> 2, t = lane & 3;
    const int wm = wid & 3, wn = wid >> 2;         // warp tile m32 x n32

    float acc[2][4][4];
#pragma unroll
    for (int mi = 0; mi < 2; mi++)
#pragma unroll
        for (int ni = 0; ni < 4; ni++)
#pragma unroll
            for (int r = 0; r < 4; r++) acc[mi][ni][r] = 0.f;

    uint32_t* Sh32 = (uint32_t*)Sh;
    uint32_t* Sl32 = (uint32_t*)Sl;
    const uint32_t* Vh32 = (const uint32_t*)Vh;
    const uint32_t* Vl32 = (const uint32_t*)Vl;

    for (int kt = 0; kt <= bm; kt++) {
        // load + split S chunk 128x128 fp32
        const float* Sg = score + ((size_t)z * TSEQ + bm * 128) * TSEQ + kt * 128;
#pragma unroll
        for (int it = 0; it < 16; it++) {
            int idx = tid + it * 256;      // 0..4095
            int r = idx >> 5;              // 0..127
            int c4 = idx & 31;             // float4 col
            float4 v = *(const float4*)&Sg[(size_t)r * TSEQ + c4 * 4];
            __nv_bfloat16 h0 = __float2bfloat16(v.x), h1 = __float2bfloat16(v.y);
            __nv_bfloat16 h2 = __float2bfloat16(v.z), h3 = __float2bfloat16(v.w);
            uint32_t* ph = &Sh32[r * 68 + c4 * 2];
            uint32_t* pl = &Sl32[r * 68 + c4 * 2];
            ph[0] = pack2(h0, h1); ph[1] = pack2(h2, h3);
            pl[0] = pack2(__float2bfloat16(v.x - __bfloat162float(h0)),
                          __float2bfloat16(v.y - __bfloat162float(h1)));
            pl[1] = pack2(__float2bfloat16(v.z - __bfloat162float(h2)),
                          __float2bfloat16(v.w - __bfloat162float(h3)));
        }
        // load + split + transpose V chunk 128(k) x 64(hd)
        const float* Vg = g_V + ((size_t)z * TSEQ + kt * 128) * HDIM;
#pragma unroll
        for (int it = 0; it < 8; it++) {
            int idx = tid + it * 256;      // 0..2047
            int r = idx >> 4;              // k row 0..127
            int c4 = idx & 15;             // float4 col
            float4 v = *(const float4*)&Vg[(size_t)r * HDIM + c4 * 4];
            float vv[4] = {v.x, v.y, v.z, v.w};
#pragma unroll
            for (int j = 0; j < 4; j++) {
                __nv_bfloat16 hh = __float2bfloat16(vv[j]);
                Vh[(c4 * 4 + j) * SROW2 + r] = hh;
                Vl[(c4 * 4 + j) * SROW2 + r] =
                    __float2bfloat16(vv[j] - __bfloat162float(hh));
            }
        }
        __syncthreads();

#pragma unroll
        for (int ks = 0; ks < 8; ks++) {
            uint32_t ah[2][4], al[2][4];
#pragma unroll
            for (int mi = 0; mi < 2; mi++) {
                int rb = wm * 32 + mi * 16 + g;
                int o0 = rb * 68 + ks * 8 + t;
                int o1 = (rb + 8) * 68 + ks * 8 + t;
                ah[mi][0] = Sh32[o0];     ah[mi][1] = Sh32[o1];
                ah[mi][2] = Sh32[o0 + 4]; ah[mi][3] = Sh32[o1 + 4];
                al[mi][0] = Sl32[o0];     al[mi][1] = Sl32[o1];
                al[mi][2] = Sl32[o0 + 4]; al[mi][3] = Sl32[o1 + 4];
            }
#pragma unroll
            for (int ni = 0; ni < 4; ni++) {
                int nb = wn * 32 + ni * 8 + g;
                int o = nb * 68 + ks * 8 + t;
                uint32_t bh0 = Vh32[o], bh1 = Vh32[o + 4];
                uint32_t bl0 = Vl32[o], bl1 = Vl32[o + 4];
#pragma unroll
                for (int mi = 0; mi < 2; mi++) {
                    mma16816(acc[mi][ni], ah[mi], bh0, bh1);
                    mma16816(acc[mi][ni], ah[mi], bl0, bl1);
                    mma16816(acc[mi][ni], al[mi], bh0, bh1);
                }
            }
        }
        __syncthreads();
    }

    // epilogue: ctx -> bf16 hi/lo [tok][1024]
#pragma unroll
    for (int mi = 0; mi < 2; mi++) {
        int tok0 = bm * 128 + wm * 32 + mi * 16 + g;
#pragma unroll
        for (int ni = 0; ni < 4; ni++) {
            int n = wn * 32 + ni * 8 + 2 * t;        // hd col (even)
            float c0 = acc[mi][ni][0], c1 = acc[mi][ni][1];
            float c2 = acc[mi][ni][2], c3 = acc[mi][ni][3];
            size_t o0 = ((size_t)b * TSEQ + tok0) * DMODEL + h * HDIM + n;
            size_t o1 = ((size_t)b * TSEQ + tok0 + 8) * DMODEL + h * HDIM + n;
            __nv_bfloat16 h0 = __float2bfloat16(c0), h1 = __float2bfloat16(c1);
            __nv_bfloat16 h2 = __float2bfloat16(c2), h3 = __float2bfloat16(c3);
            *(uint32_t*)&g_Ctxhi[o0] = pack2(h0, h1);
            *(uint32_t*)&g_Ctxlo[o0] = pack2(
                __float2bfloat16(c0 - __bfloat162float(h0)),
                __float2bfloat16(c1 - __bfloat162float(h1)));
            *(uint32_t*)&g_Ctxhi[o1] = pack2(h2, h3);
            *(uint32_t*)&g_Ctxlo[o1] = pack2(
                __float2bfloat16(c2 - __bfloat162float(h2)),
                __float2bfloat16(c3 - __bfloat162float(h3)));
        }
    }
}

// ---------------- launch ----------------
extern "C" void kernel_launch(void* const* d_in, const int* in_sizes, int n_in,
                              void* d_out, int out_size) {
    const float* x    = (const float*)d_in[0];   // [B,T,D]
    const float* Wqkv = (const float*)d_in[2];   // [D,3D]
    const float* Wout = (const float*)d_in[3];   // [D,D]
    const float* bout = (const float*)d_in[4];   // [D]

    float* out = (float*)d_out;
    const size_t outElems = (size_t)BATCH * TSEQ * DMODEL;
    const size_t scoreElems = (size_t)BH * TSEQ * TSEQ;
    float* score = ((size_t)out_size >= outElems + scoreElems)
                       ? (out + outElems)
                       : g_scoreScratch;

    const int GEMM_SMEM = 4 * TILE_ELEMS * (int)sizeof(__nv_bfloat16);        // 73728
    const int SV_SMEM = (2 * 128 * SROW2 + 2 * 64 * SROW2) * (int)sizeof(__nv_bfloat16); // 104448
    cudaFuncSetAttribute(gemm_mma<0>, cudaFuncAttributeMaxDynamicSharedMemorySize, GEMM_SMEM);
    cudaFuncSetAttribute(gemm_mma<1>, cudaFuncAttributeMaxDynamicSharedMemorySize, GEMM_SMEM);
    cudaFuncSetAttribute(w_mma,      cudaFuncAttributeMaxDynamicSharedMemorySize, GEMM_SMEM);
    cudaFuncSetAttribute(logits_mma, cudaFuncAttributeMaxDynamicSharedMemorySize, GEMM_SMEM);
    cudaFuncSetAttribute(sv_mma,     cudaFuncAttributeMaxDynamicSharedMemorySize, SV_SMEM);

    __nv_bfloat16 *xhi, *xlo, *wqh, *wql, *woh, *wol;
    cudaGetSymbolAddress((void**)&xhi, g_Xhi);
    cudaGetSymbolAddress((void**)&xlo, g_Xlo);
    cudaGetSymbolAddress((void**)&wqh, g_WqkvT_hi);
    cudaGetSymbolAddress((void**)&wql, g_WqkvT_lo);
    cudaGetSymbolAddress((void**)&woh, g_WoutT_hi);
    cudaGetSymbolAddress((void**)&wol, g_WoutT_lo);

    pe_kernel<<<(TSEQ * DMODEL) / 256, 256>>>();
    split_kernel<<<(4096 * 1024) / 256, 256>>>(x, xhi, xlo);
    transpose_split_kernel<<<dim3(3072 / 32, 1024 / 32), dim3(32, 8)>>>(Wqkv, wqh, wql, 3072);
    transpose_split_kernel<<<dim3(1024 / 32, 1024 / 32), dim3(32, 8)>>>(Wout, woh, wol, 1024);

    gemm_mma<0><<<dim3(32, 24), 256, GEMM_SMEM>>>(nullptr, nullptr);   // QKV

    w_mma<<<dim3(16, 16, 32), 256, GEMM_SMEM>>>();                     // skew GEMM
    logits_mma<<<dim3(16, 16, 32), 256, GEMM_SMEM>>>(score);
    softmax_kernel<<<BH * TSEQ, 256>>>(score);
    sv_mma<<<dim3(16, 32), 256, SV_SMEM>>>(score);

    gemm_mma<1><<<dim3(32, 8), 256, GEMM_SMEM>>>(bout, out);           // out proj
}

// round 7
// speedup vs baseline: 1.6937x; 1.0173x over previous
#include <cuda_runtime.h>
#include <cuda_bf16.h>
#include <math.h>
#include <stdint.h>

#define TSEQ   2048
#define DMODEL 1024
#define NH     16
#define HDIM   64
#define BATCH  2
#define BH     (BATCH*NH)   // 32

// ---------------- scratch (static device arrays; no allocation) ----------------
__device__ float g_V[(size_t)BH * TSEQ * HDIM];         // 16 MB  [z][t][hd] fp32
__device__ float g_W[(size_t)BH * TSEQ * TSEQ];         // 512 MB [z][q][l] skew gemm
// bf16 hi/lo operands
__device__ __nv_bfloat16 g_Qhi[(size_t)BH * TSEQ * HDIM];   // [z][t][hd]
__device__ __nv_bfloat16 g_Qlo[(size_t)BH * TSEQ * HDIM];
__device__ __nv_bfloat16 g_Khi[(size_t)BH * TSEQ * HDIM];
__device__ __nv_bfloat16 g_Klo[(size_t)BH * TSEQ * HDIM];
__device__ __nv_bfloat16 g_Ehi[(size_t)TSEQ * DMODEL];      // E[l][dim] (pos = 2047-l)
__device__ __nv_bfloat16 g_Elo[(size_t)TSEQ * DMODEL];
__device__ __nv_bfloat16 g_Xhi[(size_t)4096 * 1024];
__device__ __nv_bfloat16 g_Xlo[(size_t)4096 * 1024];
__device__ __nv_bfloat16 g_WqkvT_hi[(size_t)3072 * 1024];
__device__ __nv_bfloat16 g_WqkvT_lo[(size_t)3072 * 1024];
__device__ __nv_bfloat16 g_WoutT_hi[(size_t)1024 * 1024];
__device__ __nv_bfloat16 g_WoutT_lo[(size_t)1024 * 1024];
__device__ __nv_bfloat16 g_Ctxhi[(size_t)4096 * 1024];
__device__ __nv_bfloat16 g_Ctxlo[(size_t)4096 * 1024];
// fallback scratch in case d_out does not include the score tensor
__device__ float g_scoreScratch[(size_t)BH * TSEQ * TSEQ];

// ---------------- helpers ----------------
__device__ __forceinline__ uint32_t pack2(__nv_bfloat16 a, __nv_bfloat16 b) {
    uint16_t x = *(uint16_t*)&a, y = *(uint16_t*)&b;
    return (uint32_t)x | ((uint32_t)y << 16);
}
__device__ __forceinline__ void mma16816(float* c, const uint32_t* a,
                                         uint32_t b0, uint32_t b1) {
    asm volatile(
        "mma.sync.aligned.m16n8k16.row.col.f32.bf16.bf16.f32 "
        "{%0,%1,%2,%3}, {%4,%5,%6,%7}, {%8,%9}, {%0,%1,%2,%3};"
        : "+f"(c[0]), "+f"(c[1]), "+f"(c[2]), "+f"(c[3])
        : "r"(a[0]), "r"(a[1]), "r"(a[2]), "r"(a[3]), "r"(b0), "r"(b1));
}
__device__ __forceinline__ void cp16(void* smem_dst, const void* gmem_src) {
    uint32_t d = (uint32_t)__cvta_generic_to_shared(smem_dst);
    asm volatile("cp.async.cg.shared.global [%0], [%1], 16;" :: "r"(d), "l"(gmem_src));
}
#define CP_COMMIT() asm volatile("cp.async.commit_group;" ::: "memory")
#define CP_WAIT0()  asm volatile("cp.async.wait_group 0;" ::: "memory")
#define CP_WAIT1()  asm volatile("cp.async.wait_group 1;" ::: "memory")

// ---------------- 1) relative PE table as bf16 hi/lo (E layout: row l, pos=2047-l) ----
__global__ void pe_kernel() {
    int idx = blockIdx.x * 256 + threadIdx.x;
    int l   = idx >> 10;
    int dim = idx & (DMODEL - 1);
    int pos = (TSEQ - 1) - l;
    int i2  = dim & ~1;
    float div = __expf(-9.210340371976184f * (float)i2 * (1.0f / (float)DMODEL));
    float ang = (float)pos * div;
    float v = (dim & 1) ? cosf(ang) : sinf(ang);
    __nv_bfloat16 h = __float2bfloat16(v);
    g_Ehi[idx] = h;
    g_Elo[idx] = __float2bfloat16(v - __bfloat162float(h));
}

// ---------------- bf16 split: v = hi + lo ----------------
__global__ void split_kernel(const float* __restrict__ src,
                             __nv_bfloat16* __restrict__ hi,
                             __nv_bfloat16* __restrict__ lo) {
    int idx = blockIdx.x * 256 + threadIdx.x;
    float v = src[idx];
    __nv_bfloat16 h = __float2bfloat16(v);
    hi[idx] = h;
    lo[idx] = __float2bfloat16(v - __bfloat162float(h));
}

// ---------------- transpose + split: W[K=1024][C] -> T[C][1024] hi/lo ----------------
__global__ void transpose_split_kernel(const float* __restrict__ W,
                                       __nv_bfloat16* __restrict__ thi,
                                       __nv_bfloat16* __restrict__ tlo, int C) {
    __shared__ float tile[32][33];
    int c0 = blockIdx.x * 32, k0 = blockIdx.y * 32;
    int tx = threadIdx.x, ty = threadIdx.y;       // block (32, 8)
#pragma unroll
    for (int i = 0; i < 32; i += 8)
        tile[ty + i][tx] = W[(size_t)(k0 + ty + i) * C + c0 + tx];
    __syncthreads();
#pragma unroll
    for (int i = 0; i < 32; i += 8) {
        float v = tile[tx][ty + i];
        size_t o = (size_t)(c0 + ty + i) * 1024 + k0 + tx;
        __nv_bfloat16 h = __float2bfloat16(v);
        thi[o] = h;
        tlo[o] = __float2bfloat16(v - __bfloat162float(h));
    }
}

// ================= smem tile loading (cp.async) =================
#define SROW 72                // padded smem row (64 data + 8), stride32 = 36
#define TILE_ELEMS (128 * SROW)

__device__ __forceinline__ void ld_tile_async(const __nv_bfloat16* __restrict__ src,
                                              size_t stride,
                                              __nv_bfloat16* __restrict__ dst, int tid) {
#pragma unroll
    for (int it = 0; it < 4; ++it) {
        int idx = tid + it * 256;      // 0..1023
        int r = idx >> 3;              // 0..127
        int c = idx & 7;               // 0..7 (16B chunks)
        cp16(dst + r * SROW + c * 8, src + (size_t)r * stride + c * 8);
    }
}

// ================= big GEMMs (qkv / outproj), cp.async double-buffered ============
// MODE 0: qkv  (A = X, B = WqkvT; emit Qhi/lo, Khi/lo bf16 + V fp32)
// MODE 1: out  (A = Ctx hi/lo, B = WoutT; out = C + bias)
template <int MODE>
__global__ void __launch_bounds__(256, 1) gemm_mma(const float* __restrict__ bias,
                                                   float* __restrict__ outp) {
    extern __shared__ __nv_bfloat16 sm[];   // 2 stages x 4 tiles

    const int tid = threadIdx.x;
    const int wid = tid >> 5, lane = tid & 31;
    const int g = lane >> 2, t = lane & 3;
    const int wm = wid & 1, wn = wid >> 1;
    const int bm = blockIdx.x;                  // token tile   (x128)
    const int bn = blockIdx.y;                  // feature tile (x128)

    const __nv_bfloat16* Agh = (MODE == 0 ? g_Xhi : g_Ctxhi) + (size_t)(bm * 128) * 1024;
    const __nv_bfloat16* Agl = (MODE == 0 ? g_Xlo : g_Ctxlo) + (size_t)(bm * 128) * 1024;
    const __nv_bfloat16* Bgh = (MODE == 0 ? g_WqkvT_hi : g_WoutT_hi) + (size_t)(bn * 128) * 1024;
    const __nv_bfloat16* Bgl = (MODE == 0 ? g_WqkvT_lo : g_WoutT_lo) + (size_t)(bn * 128) * 1024;

    float acc[4][4][4];
#pragma unroll
    for (int mi = 0; mi < 4; mi++)
#pragma unroll
        for (int ni = 0; ni < 4; ni++)
#pragma unroll
            for (int r = 0; r < 4; r++) acc[mi][ni][r] = 0.f;

    auto issue = [&](int kc, int s) {
        __nv_bfloat16* st = sm + s * 4 * TILE_ELEMS;
        ld_tile_async(Agh + kc * 64, 1024, st, tid);
        ld_tile_async(Agl + kc * 64, 1024, st + TILE_ELEMS, tid);
        ld_tile_async(Bgh + kc * 64, 1024, st + 2 * TILE_ELEMS, tid);
        ld_tile_async(Bgl + kc * 64, 1024, st + 3 * TILE_ELEMS, tid);
        CP_COMMIT();
    };

    issue(0, 0);
    for (int kc = 0; kc < 16; kc++) {
        int s = kc & 1;
        if (kc < 15) { issue(kc + 1, s ^ 1); CP_WAIT1(); }
        else         { CP_WAIT0(); }
        __syncthreads();

        const uint32_t* Ah32 = (const uint32_t*)(sm + s * 4 * TILE_ELEMS);
        const uint32_t* Al32 = Ah32 + TILE_ELEMS / 2;
        const uint32_t* Bh32 = Ah32 + TILE_ELEMS;
        const uint32_t* Bl32 = Ah32 + 3 * TILE_ELEMS / 2;

#pragma unroll
        for (int ks = 0; ks < 4; ks++) {
            uint32_t ah[4][4], al[4][4];
#pragma unroll
            for (int mi = 0; mi < 4; mi++) {
                int rb = wm * 64 + mi * 16 + g;
                int o0 = rb * 36 + ks * 8 + t;
                int o1 = (rb + 8) * 36 + ks * 8 + t;
                ah[mi][0] = Ah32[o0];     ah[mi][1] = Ah32[o1];
                ah[mi][2] = Ah32[o0 + 4]; ah[mi][3] = Ah32[o1 + 4];
                al[mi][0] = Al32[o0];     al[mi][1] = Al32[o1];
                al[mi][2] = Al32[o0 + 4]; al[mi][3] = Al32[o1 + 4];
            }
#pragma unroll
            for (int ni = 0; ni < 4; ni++) {
                int nb = wn * 32 + ni * 8 + g;
                int o = nb * 36 + ks * 8 + t;
                uint32_t bh0 = Bh32[o], bh1 = Bh32[o + 4];
                uint32_t bl0 = Bl32[o], bl1 = Bl32[o + 4];
#pragma unroll
                for (int mi = 0; mi < 4; mi++) {
                    mma16816(acc[mi][ni], ah[mi], bh0, bh1);
                    mma16816(acc[mi][ni], ah[mi], bl0, bl1);
                    mma16816(acc[mi][ni], al[mi], bh0, bh1);
                }
            }
        }
        __syncthreads();
    }

    // ---------------- epilogue ----------------
#pragma unroll
    for (int mi = 0; mi < 4; mi++) {
        int m0 = bm * 128 + wm * 64 + mi * 16 + g;
#pragma unroll
        for (int ni = 0; ni < 4; ni++) {
            int n = bn * 128 + wn * 32 + ni * 8 + 2 * t;   // feature col (even)
            float c0 = acc[mi][ni][0], c1 = acc[mi][ni][1];
            float c2 = acc[mi][ni][2], c3 = acc[mi][ni][3];
            if (MODE == 0) {
                int sect = n >> 10, h = (n >> 6) & (NH - 1), hd = n & 63;
                int b0 = m0 >> 11, t0 = m0 & (TSEQ - 1);
                int m1 = m0 + 8, b1 = m1 >> 11, t1 = m1 & (TSEQ - 1);
                size_t i0 = (((size_t)b0 * NH + h) * TSEQ + t0) * HDIM + hd;
                size_t i1 = (((size_t)b1 * NH + h) * TSEQ + t1) * HDIM + hd;
                if (sect == 2) {
                    *(float2*)&g_V[i0] = make_float2(c0, c1);
                    *(float2*)&g_V[i1] = make_float2(c2, c3);
                } else {
                    __nv_bfloat16* Dh = sect ? g_Khi : g_Qhi;
                    __nv_bfloat16* Dl = sect ? g_Klo : g_Qlo;
                    __nv_bfloat16 h0 = __float2bfloat16(c0), h1 = __float2bfloat16(c1);
                    __nv_bfloat16 h2 = __float2bfloat16(c2), h3 = __float2bfloat16(c3);
                    *(uint32_t*)&Dh[i0] = pack2(h0, h1);
                    *(uint32_t*)&Dl[i0] = pack2(
                        __float2bfloat16(c0 - __bfloat162float(h0)),
                        __float2bfloat16(c1 - __bfloat162float(h1)));
                    *(uint32_t*)&Dh[i1] = pack2(h2, h3);
                    *(uint32_t*)&Dl[i1] = pack2(
                        __float2bfloat16(c2 - __bfloat162float(h2)),
                        __float2bfloat16(c3 - __bfloat162float(h3)));
                }
            } else {
                float2 bb = *(const float2*)&bias[n];
                *(float2*)&outp[(size_t)m0 * 1024 + n] = make_float2(c0 + bb.x, c1 + bb.y);
                *(float2*)&outp[(size_t)(m0 + 8) * 1024 + n] = make_float2(c2 + bb.x, c3 + bb.y);
            }
        }
    }
}

// ================= shared single-chunk (K=64) mma core for W & logits =============
__device__ __forceinline__ void mma_k64(float acc[4][4][4],
                                        const uint32_t* Ah32, const uint32_t* Al32,
                                        const uint32_t* Bh32, const uint32_t* Bl32,
                                        int wm, int wn, int g, int t) {
#pragma unroll
    for (int ks = 0; ks < 4; ks++) {
        uint32_t ah[4][4], al[4][4];
#pragma unroll
        for (int mi = 0; mi < 4; mi++) {
            int rb = wm * 64 + mi * 16 + g;
            int o0 = rb * 36 + ks * 8 + t;
            int o1 = (rb + 8) * 36 + ks * 8 + t;
            ah[mi][0] = Ah32[o0];     ah[mi][1] = Ah32[o1];
            ah[mi][2] = Ah32[o0 + 4]; ah[mi][3] = Ah32[o1 + 4];
            al[mi][0] = Al32[o0];     al[mi][1] = Al32[o1];
            al[mi][2] = Al32[o0 + 4]; al[mi][3] = Al32[o1 + 4];
        }
#pragma unroll
        for (int ni = 0; ni < 4; ni++) {
            int nb = wn * 32 + ni * 8 + g;
            int o = nb * 36 + ks * 8 + t;
            uint32_t bh0 = Bh32[o], bh1 = Bh32[o + 4];
            uint32_t bl0 = Bl32[o], bl1 = Bl32[o + 4];
#pragma unroll
            for (int mi = 0; mi < 4; mi++) {
                mma16816(acc[mi][ni], ah[mi], bh0, bh1);
                mma16816(acc[mi][ni], ah[mi], bl0, bl1);
                mma16816(acc[mi][ni], al[mi], bh0, bh1);
            }
        }
    }
}

// ---------------- W = Q @ E^T per head (skew GEMM), needed tiles only ------------
__global__ void __launch_bounds__(256, 1) w_mma() {
    const int ln = blockIdx.x;     // l tile
    const int bm = blockIdx.y;     // q tile
    if (ln < 15 - bm) return;      // unneeded tile
    const int z = blockIdx.z;
    const int h = z & (NH - 1);

    extern __shared__ __nv_bfloat16 smw[];
    __nv_bfloat16* Qh = smw;
    __nv_bfloat16* Ql = smw + TILE_ELEMS;
    __nv_bfloat16* Ehs = smw + 2 * TILE_ELEMS;
    __nv_bfloat16* Els = smw + 3 * TILE_ELEMS;

    const int tid = threadIdx.x;
    const int wid = tid >> 5, lane = tid & 31;
    const int g = lane >> 2, t = lane & 3;
    const int wm = wid & 1, wn = wid >> 1;

    ld_tile_async(g_Qhi + ((size_t)z * TSEQ + bm * 128) * HDIM, 64, Qh, tid);
    ld_tile_async(g_Qlo + ((size_t)z * TSEQ + bm * 128) * HDIM, 64, Ql, tid);
    ld_tile_async(g_Ehi + (size_t)(ln * 128) * DMODEL + h * HDIM, 1024, Ehs, tid);
    ld_tile_async(g_Elo + (size_t)(ln * 128) * DMODEL + h * HDIM, 1024, Els, tid);
    CP_COMMIT();
    CP_WAIT0();
    __syncthreads();

    float acc[4][4][4];
#pragma unroll
    for (int mi = 0; mi < 4; mi++)
#pragma unroll
        for (int ni = 0; ni < 4; ni++)
#pragma unroll
            for (int r = 0; r < 4; r++) acc[mi][ni][r] = 0.f;

    mma_k64(acc, (const uint32_t*)Qh, (const uint32_t*)Ql,
            (const uint32_t*)Ehs, (const uint32_t*)Els, wm, wn, g, t);

    float* Wz = g_W + (size_t)z * TSEQ * TSEQ;
#pragma unroll
    for (int mi = 0; mi < 4; mi++) {
        int q0 = bm * 128 + wm * 64 + mi * 16 + g;
#pragma unroll
        for (int ni = 0; ni < 4; ni++) {
            int l = ln * 128 + wn * 32 + ni * 8 + 2 * t;
            *(float2*)&Wz[(size_t)q0 * TSEQ + l] =
                make_float2(acc[mi][ni][0], acc[mi][ni][1]);
            *(float2*)&Wz[(size_t)(q0 + 8) * TSEQ + l] =
                make_float2(acc[mi][ni][2], acc[mi][ni][3]);
        }
    }
}

// ---------------- logits = (Q@K^T + gather(W)) / 8, causal tiles -----------------
__global__ void __launch_bounds__(256, 1) logits_mma(float* __restrict__ score) {
    const int bn = blockIdx.x;     // k tile
    const int bm = blockIdx.y;     // q tile
    if (bn > bm) return;
    const int z = blockIdx.z;

    extern __shared__ __nv_bfloat16 sml[];
    __nv_bfloat16* Qh = sml;
    __nv_bfloat16* Ql = sml + TILE_ELEMS;
    __nv_bfloat16* Kh = sml + 2 * TILE_ELEMS;
    __nv_bfloat16* Kl = sml + 3 * TILE_ELEMS;

    const int tid = threadIdx.x;
    const int wid = tid >> 5, lane = tid & 31;
    const int g = lane >> 2, t = lane & 3;
    const int wm = wid & 1, wn = wid >> 1;

    ld_tile_async(g_Qhi + ((size_t)z * TSEQ + bm * 128) * HDIM, 64, Qh, tid);
    ld_tile_async(g_Qlo + ((size_t)z * TSEQ + bm * 128) * HDIM, 64, Ql, tid);
    ld_tile_async(g_Khi + ((size_t)z * TSEQ + bn * 128) * HDIM, 64, Kh, tid);
    ld_tile_async(g_Klo + ((size_t)z * TSEQ + bn * 128) * HDIM, 64, Kl, tid);
    CP_COMMIT();
    CP_WAIT0();
    __syncthreads();

    float acc[4][4][4];
#pragma unroll
    for (int mi = 0; mi < 4; mi++)
#pragma unroll
        for (int ni = 0; ni < 4; ni++)
#pragma unroll
            for (int r = 0; r < 4; r++) acc[mi][ni][r] = 0.f;

    mma_k64(acc, (const uint32_t*)Qh, (const uint32_t*)Ql,
            (const uint32_t*)Kh, (const uint32_t*)Kl, wm, wn, g, t);

    const float* Wz = g_W + (size_t)z * TSEQ * TSEQ;
    const float inv_scale = 0.125f;
#pragma unroll
    for (int mi = 0; mi < 4; mi++) {
        int q0 = bm * 128 + wm * 64 + mi * 16 + g;
        int q1 = q0 + 8;
#pragma unroll
        for (int ni = 0; ni < 4; ni++) {
            int k0 = bn * 128 + wn * 32 + ni * 8 + 2 * t;
            // att_e[q][k] = W[q][2047 - q + k]  (masked cols read garbage; softmax zeroes)
            float e0 = Wz[(size_t)q0 * TSEQ + (2047 - q0 + k0)];
            float e1 = Wz[(size_t)q0 * TSEQ + (2047 - q0 + k0 + 1)];
            float e2 = Wz[(size_t)q1 * TSEQ + (2047 - q1 + k0)];
            float e3 = Wz[(size_t)q1 * TSEQ + (2047 - q1 + k0 + 1)];
            *(float2*)&score[((size_t)z * TSEQ + q0) * TSEQ + k0] =
                make_float2((acc[mi][ni][0] + e0) * inv_scale,
                            (acc[mi][ni][1] + e1) * inv_scale);
            *(float2*)&score[((size_t)z * TSEQ + q1) * TSEQ + k0] =
                make_float2((acc[mi][ni][2] + e2) * inv_scale,
                            (acc[mi][ni][3] + e3) * inv_scale);
        }
    }
}

// ---------------- causal row softmax, in-place; zeros for k>q ----------------
__global__ void __launch_bounds__(256) softmax_kernel(float* __restrict__ score) {
    size_t row = blockIdx.x;
    int q = (int)(row & (TSEQ - 1));
    float* p = &score[row * TSEQ];
    int tid = threadIdx.x;

    __shared__ float red[8];
    float v[8];
    float mx = -1e30f;
#pragma unroll
    for (int i = 0; i < 8; i++) {
        int k = i * 256 + tid;
        v[i] = -1e30f;
        if (k <= q) { v[i] = p[k]; mx = fmaxf(mx, v[i]); }
    }
#pragma unroll
    for (int o = 16; o > 0; o >>= 1) mx = fmaxf(mx, __shfl_xor_sync(0xffffffffu, mx, o));
    if ((tid & 31) == 0) red[tid >> 5] = mx;
    __syncthreads();
    float bmx = red[0];
#pragma unroll
    for (int w = 1; w < 8; w++) bmx = fmaxf(bmx, red[w]);

    float s = 0.f;
#pragma unroll
    for (int i = 0; i < 8; i++) {
        int k = i * 256 + tid;
        float e = (k <= q) ? __expf(v[i] - bmx) : 0.f;
        v[i] = e;
        s += e;
    }
#pragma unroll
    for (int o = 16; o > 0; o >>= 1) s += __shfl_xor_sync(0xffffffffu, s, o);
    __syncthreads();
    if ((tid & 31) == 0) red[tid >> 5] = s;
    __syncthreads();
    float tot = 0.f;
#pragma unroll
    for (int w = 0; w < 8; w++) tot += red[w];
    float inv = 1.0f / tot;
#pragma unroll
    for (int i = 0; i < 8; i++) {
        int k = i * 256 + tid;
        p[k] = v[i] * inv;
    }
}

// ---------------- ctx = S @ V via mma, cp.async staged -----------------------
// per CTA: q tile 128 x full hd 64, loop causal k chunks of 128.
#define SROW2 136               // 128 data + 8 pad; stride32 = 68
#define SV_BF16_ELEMS (2 * 128 * SROW2 + 2 * 64 * SROW2)   // 52224 bf16 = 104448 B
__global__ void __launch_bounds__(256, 1) sv_mma(const float* __restrict__ score) {
    const int bm = blockIdx.x;     // q tile
    const int z  = blockIdx.y;
    const int b  = z >> 4, h = z & (NH - 1);

    extern __shared__ __nv_bfloat16 smv[];
    __nv_bfloat16* Sh = smv;                       // [128][136]
    __nv_bfloat16* Sl = smv + 128 * SROW2;
    __nv_bfloat16* Vh = smv + 2 * 128 * SROW2;     // [64][136] (transposed: [hd][k])
    __nv_bfloat16* Vl = Vh + 64 * SROW2;
    float* stgS = (float*)(smv + SV_BF16_ELEMS);   // [128][128] fp32
    float* stgV = stgS + 128 * 128;                // [128][64]  fp32

    const int tid = threadIdx.x;
    const int wid = tid >> 5, lane = tid & 31;
    const int g = lane >> 2, t = lane & 3;
    const int wm = wid & 3, wn = wid >> 2;         // warp tile m32 x n32

    float acc[2][4][4];
#pragma unroll
    for (int mi = 0; mi < 2; mi++)
#pragma unroll
        for (int ni = 0; ni < 4; ni++)
#pragma unroll
            for (int r = 0; r < 4; r++) acc[mi][ni][r] = 0.f;

    uint32_t* Sh32 = (uint32_t*)Sh;
    uint32_t* Sl32 = (uint32_t*)Sl;
    const uint32_t* Vh32 = (const uint32_t*)Vh;
    const uint32_t* Vl32 = (const uint32_t*)Vl;

    auto issue_chunk = [&](int kt) {
        const float* Sg = score + ((size_t)z * TSEQ + bm * 128) * TSEQ + kt * 128;
#pragma unroll
        for (int it = 0; it < 16; it++) {
            int idx = tid + it * 256;      // 0..4095
            int r = idx >> 5;              // 0..127
            int c4 = idx & 31;
            cp16(stgS + r * 128 + c4 * 4, Sg + (size_t)r * TSEQ + c4 * 4);
        }
        const float* Vg = g_V + ((size_t)z * TSEQ + kt * 128) * HDIM;
#pragma unroll
        for (int it = 0; it < 8; it++) {
            int idx = tid + it * 256;      // 0..2047
            int r = idx >> 4;              // 0..127
            int c4 = idx & 15;
            cp16(stgV + r * 64 + c4 * 4, Vg + (size_t)r * HDIM + c4 * 4);
        }
        CP_COMMIT();
    };

    issue_chunk(0);
    for (int kt = 0; kt <= bm; kt++) {
        CP_WAIT0();
        __syncthreads();                   // staging ready for all

        // split staging -> bf16 smem
#pragma unroll
        for (int it = 0; it < 16; it++) {
            int idx = tid + it * 256;
            int r = idx >> 5;
            int c4 = idx & 31;
            float4 v = *(const float4*)&stgS[r * 128 + c4 * 4];
            __nv_bfloat16 h0 = __float2bfloat16(v.x), h1 = __float2bfloat16(v.y);
            __nv_bfloat16 h2 = __float2bfloat16(v.z), h3 = __float2bfloat16(v.w);
            uint32_t* ph = &Sh32[r * 68 + c4 * 2];
            uint32_t* pl = &Sl32[r * 68 + c4 * 2];
            ph[0] = pack2(h0, h1); ph[1] = pack2(h2, h3);
            pl[0] = pack2(__float2bfloat16(v.x - __bfloat162float(h0)),
                          __float2bfloat16(v.y - __bfloat162float(h1)));
            pl[1] = pack2(__float2bfloat16(v.z - __bfloat162float(h2)),
                          __float2bfloat16(v.w - __bfloat162float(h3)));
        }
#pragma unroll
        for (int it = 0; it < 8; it++) {
            int idx = tid + it * 256;
            int r = idx >> 4;              // k row 0..127
            int c4 = idx & 15;
            float4 v = *(const float4*)&stgV[r * 64 + c4 * 4];
            float vv[4] = {v.x, v.y, v.z, v.w};
#pragma unroll
            for (int j = 0; j < 4; j++) {
                __nv_bfloat16 hh = __float2bfloat16(vv[j]);
                Vh[(c4 * 4 + j) * SROW2 + r] = hh;
                Vl[(c4 * 4 + j) * SROW2 + r] =
                    __float2bfloat16(vv[j] - __bfloat162float(hh));
            }
        }
        __syncthreads();                   // bf16 bufs ready; staging consumed

        if (kt < bm) issue_chunk(kt + 1);  // overlap fetch with mma

#pragma unroll
        for (int ks = 0; ks < 8; ks++) {
            uint32_t ah[2][4], al[2][4];
#pragma unroll
            for (int mi = 0; mi < 2; mi++) {
                int rb = wm * 32 + mi * 16 + g;
                int o0 = rb * 68 + ks * 8 + t;
                int o1 = (rb + 8) * 68 + ks * 8 + t;
                ah[mi][0] = Sh32[o0];     ah[mi][1] = Sh32[o1];
                ah[mi][2] = Sh32[o0 + 4]; ah[mi][3] = Sh32[o1 + 4];
                al[mi][0] = Sl32[o0];     al[mi][1] = Sl32[o1];
                al[mi][2] = Sl32[o0 + 4]; al[mi][3] = Sl32[o1 + 4];
            }
#pragma unroll
            for (int ni = 0; ni < 4; ni++) {
                int nb = wn * 32 + ni * 8 + g;
                int o = nb * 68 + ks * 8 + t;
                uint32_t bh0 = Vh32[o], bh1 = Vh32[o + 4];
                uint32_t bl0 = Vl32[o], bl1 = Vl32[o + 4];
#pragma unroll
                for (int mi = 0; mi < 2; mi++) {
                    mma16816(acc[mi][ni], ah[mi], bh0, bh1);
                    mma16816(acc[mi][ni], ah[mi], bl0, bl1);
                    mma16816(acc[mi][ni], al[mi], bh0, bh1);
                }
            }
        }
        __syncthreads();                   // mma reads done before next split
    }

    // epilogue: ctx -> bf16 hi/lo [tok][1024]
#pragma unroll
    for (int mi = 0; mi < 2; mi++) {
        int tok0 = bm * 128 + wm * 32 + mi * 16 + g;
#pragma unroll
        for (int ni = 0; ni < 4; ni++) {
            int n = wn * 32 + ni * 8 + 2 * t;        // hd col (even)
            float c0 = acc[mi][ni][0], c1 = acc[mi][ni][1];
            float c2 = acc[mi][ni][2], c3 = acc[mi][ni][3];
            size_t o0 = ((size_t)b * TSEQ + tok0) * DMODEL + h * HDIM + n;
            size_t o1 = ((size_t)b * TSEQ + tok0 + 8) * DMODEL + h * HDIM + n;
            __nv_bfloat16 h0 = __float2bfloat16(c0), h1 = __float2bfloat16(c1);
            __nv_bfloat16 h2 = __float2bfloat16(c2), h3 = __float2bfloat16(c3);
            *(uint32_t*)&g_Ctxhi[o0] = pack2(h0, h1);
            *(uint32_t*)&g_Ctxlo[o0] = pack2(
                __float2bfloat16(c0 - __bfloat162float(h0)),
                __float2bfloat16(c1 - __bfloat162float(h1)));
            *(uint32_t*)&g_Ctxhi[o1] = pack2(h2, h3);
            *(uint32_t*)&g_Ctxlo[o1] = pack2(
                __float2bfloat16(c2 - __bfloat162float(h2)),
                __float2bfloat16(c3 - __bfloat162float(h3)));
        }
    }
}

// ---------------- launch ----------------
extern "C" void kernel_launch(void* const* d_in, const int* in_sizes, int n_in,
                              void* d_out, int out_size) {
    const float* x    = (const float*)d_in[0];   // [B,T,D]
    const float* Wqkv = (const float*)d_in[2];   // [D,3D]
    const float* Wout = (const float*)d_in[3];   // [D,D]
    const float* bout = (const float*)d_in[4];   // [D]

    float* out = (float*)d_out;
    const size_t outElems = (size_t)BATCH * TSEQ * DMODEL;
    const size_t scoreElems = (size_t)BH * TSEQ * TSEQ;
    float* score = ((size_t)out_size >= outElems + scoreElems)
                       ? (out + outElems)
                       : g_scoreScratch;

    const int TILE1_SMEM = 4 * TILE_ELEMS * (int)sizeof(__nv_bfloat16);       // 73728
    const int GEMM_SMEM = 2 * TILE1_SMEM;                                     // 147456
    const int SV_SMEM = SV_BF16_ELEMS * (int)sizeof(__nv_bfloat16)
                        + (128 * 128 + 128 * 64) * (int)sizeof(float);        // 202752
    cudaFuncSetAttribute(gemm_mma<0>, cudaFuncAttributeMaxDynamicSharedMemorySize, GEMM_SMEM);
    cudaFuncSetAttribute(gemm_mma<1>, cudaFuncAttributeMaxDynamicSharedMemorySize, GEMM_SMEM);
    cudaFuncSetAttribute(w_mma,      cudaFuncAttributeMaxDynamicSharedMemorySize, TILE1_SMEM);
    cudaFuncSetAttribute(logits_mma, cudaFuncAttributeMaxDynamicSharedMemorySize, TILE1_SMEM);
    cudaFuncSetAttribute(sv_mma,     cudaFuncAttributeMaxDynamicSharedMemorySize, SV_SMEM);

    __nv_bfloat16 *xhi, *xlo, *wqh, *wql, *woh, *wol;
    cudaGetSymbolAddress((void**)&xhi, g_Xhi);
    cudaGetSymbolAddress((void**)&xlo, g_Xlo);
    cudaGetSymbolAddress((void**)&wqh, g_WqkvT_hi);
    cudaGetSymbolAddress((void**)&wql, g_WqkvT_lo);
    cudaGetSymbolAddress((void**)&woh, g_WoutT_hi);
    cudaGetSymbolAddress((void**)&wol, g_WoutT_lo);

    pe_kernel<<<(TSEQ * DMODEL) / 256, 256>>>();
    split_kernel<<<(4096 * 1024) / 256, 256>>>(x, xhi, xlo);
    transpose_split_kernel<<<dim3(3072 / 32, 1024 / 32), dim3(32, 8)>>>(Wqkv, wqh, wql, 3072);
    transpose_split_kernel<<<dim3(1024 / 32, 1024 / 32), dim3(32, 8)>>>(Wout, woh, wol, 1024);

    gemm_mma<0><<<dim3(32, 24), 256, GEMM_SMEM>>>(nullptr, nullptr);   // QKV

    w_mma<<<dim3(16, 16, 32), 256, TILE1_SMEM>>>();                    // skew GEMM
    logits_mma<<<dim3(16, 16, 32), 256, TILE1_SMEM>>>(score);
    softmax_kernel<<<BH * TSEQ, 256>>>(score);
    sv_mma<<<dim3(16, 32), 256, SV_SMEM>>>(score);

    gemm_mma<1><<<dim3(32, 8), 256, GEMM_SMEM>>>(bout, out);           // out proj
}

// round 8
// speedup vs baseline: 2.0780x; 1.2269x over previous
#include <cuda_runtime.h>
#include <cuda_bf16.h>
#include <math.h>
#include <stdint.h>

#define TSEQ   2048
#define DMODEL 1024
#define NH     16
#define HDIM   64
#define BATCH  2
#define BH     (BATCH*NH)   // 32

// ---------------- scratch (static device arrays; no allocation) ----------------
__device__ float g_V[(size_t)BH * TSEQ * HDIM];          // 16 MB  [z][t][hd] fp32
__device__ float g_Qf[(size_t)BH * TSEQ * HDIM];         // 16 MB  fp32 Q (for ae)
// combined logits operands: [z][t][128] = (Q|A~) and (K|B~), bf16 hi/lo
__device__ __nv_bfloat16 g_QAhi[(size_t)BH * TSEQ * 128];
__device__ __nv_bfloat16 g_QAlo[(size_t)BH * TSEQ * 128];
__device__ __nv_bfloat16 g_KBhi[(size_t)BH * TSEQ * 128];
__device__ __nv_bfloat16 g_KBlo[(size_t)BH * TSEQ * 128];
// big-GEMM operands
__device__ __nv_bfloat16 g_Xhi[(size_t)4096 * 1024];
__device__ __nv_bfloat16 g_Xlo[(size_t)4096 * 1024];
__device__ __nv_bfloat16 g_WqkvT_hi[(size_t)3072 * 1024];
__device__ __nv_bfloat16 g_WqkvT_lo[(size_t)3072 * 1024];
__device__ __nv_bfloat16 g_WoutT_hi[(size_t)1024 * 1024];
__device__ __nv_bfloat16 g_WoutT_lo[(size_t)1024 * 1024];
__device__ __nv_bfloat16 g_Ctxhi[(size_t)4096 * 1024];
__device__ __nv_bfloat16 g_Ctxlo[(size_t)4096 * 1024];
// fallback scratch in case d_out does not include the score tensor
__device__ float g_scoreScratch[(size_t)BH * TSEQ * TSEQ];

// ---------------- helpers ----------------
__device__ __forceinline__ uint32_t pack2(__nv_bfloat16 a, __nv_bfloat16 b) {
    uint16_t x = *(uint16_t*)&a, y = *(uint16_t*)&b;
    return (uint32_t)x | ((uint32_t)y << 16);
}
__device__ __forceinline__ void split_write(__nv_bfloat16* hi, __nv_bfloat16* lo,
                                            size_t o, float a, float b) {
    __nv_bfloat16 h0 = __float2bfloat16(a), h1 = __float2bfloat16(b);
    *(uint32_t*)&hi[o] = pack2(h0, h1);
    *(uint32_t*)&lo[o] = pack2(__float2bfloat16(a - __bfloat162float(h0)),
                               __float2bfloat16(b - __bfloat162float(h1)));
}
__device__ __forceinline__ void mma16816(float* c, const uint32_t* a,
                                         uint32_t b0, uint32_t b1) {
    asm volatile(
        "mma.sync.aligned.m16n8k16.row.col.f32.bf16.bf16.f32 "
        "{%0,%1,%2,%3}, {%4,%5,%6,%7}, {%8,%9}, {%0,%1,%2,%3};"
        : "+f"(c[0]), "+f"(c[1]), "+f"(c[2]), "+f"(c[3])
        : "r"(a[0]), "r"(a[1]), "r"(a[2]), "r"(a[3]), "r"(b0), "r"(b1));
}
__device__ __forceinline__ void cp16(void* smem_dst, const void* gmem_src) {
    uint32_t d = (uint32_t)__cvta_generic_to_shared(smem_dst);
    asm volatile("cp.async.cg.shared.global [%0], [%1], 16;" :: "r"(d), "l"(gmem_src));
}
#define CP_COMMIT() asm volatile("cp.async.commit_group;" ::: "memory")
#define CP_WAIT0()  asm volatile("cp.async.wait_group 0;" ::: "memory")
#define CP_WAIT1()  asm volatile("cp.async.wait_group 1;" ::: "memory")

// ---------------- bf16 split: v = hi + lo ----------------
__global__ void split_kernel(const float* __restrict__ src,
                             __nv_bfloat16* __restrict__ hi,
                             __nv_bfloat16* __restrict__ lo) {
    int idx = blockIdx.x * 256 + threadIdx.x;
    float v = src[idx];
    __nv_bfloat16 h = __float2bfloat16(v);
    hi[idx] = h;
    lo[idx] = __float2bfloat16(v - __bfloat162float(h));
}

// ---------------- transpose + split: W[K=1024][C] -> T[C][1024] hi/lo ----------------
__global__ void transpose_split_kernel(const float* __restrict__ W,
                                       __nv_bfloat16* __restrict__ thi,
                                       __nv_bfloat16* __restrict__ tlo, int C) {
    __shared__ float tile[32][33];
    int c0 = blockIdx.x * 32, k0 = blockIdx.y * 32;
    int tx = threadIdx.x, ty = threadIdx.y;       // block (32, 8)
#pragma unroll
    for (int i = 0; i < 32; i += 8)
        tile[ty + i][tx] = W[(size_t)(k0 + ty + i) * C + c0 + tx];
    __syncthreads();
#pragma unroll
    for (int i = 0; i < 32; i += 8) {
        float v = tile[tx][ty + i];
        size_t o = (size_t)(c0 + ty + i) * 1024 + k0 + tx;
        __nv_bfloat16 h = __float2bfloat16(v);
        thi[o] = h;
        tlo[o] = __float2bfloat16(v - __bfloat162float(h));
    }
}

// ---------------- B~ table: KB[z][k][64+2j]=cos(k*w_j), [64+2j+1]=sin(k*w_j) ------
__global__ void kb_kernel() {
    int idx = blockIdx.x * 256 + threadIdx.x;    // BH*TSEQ*32 threads
    int j = idx & 31;
    int t = (idx >> 5) & (TSEQ - 1);
    int z = idx >> 16;                            // 5+11 bits
    int h = z & (NH - 1);
    float w = __expf(-9.210340371976184f * (float)(64 * h + 2 * j) * (1.0f / 1024.0f));
    float s, c;
    sincosf((float)t * w, &s, &c);
    size_t o = ((size_t)z * TSEQ + t) * 128 + 64 + 2 * j;
    split_write(g_KBhi, g_KBlo, o, c, s);
}

// ---------------- A~ from fp32 Q: QA[z][q][64+2j], [64+2j+1] ----------------------
__global__ void ae_kernel() {
    int idx = blockIdx.x * 256 + threadIdx.x;    // BH*TSEQ*32 threads
    int j = idx & 31;
    int t = (idx >> 5) & (TSEQ - 1);
    int z = idx >> 16;
    int h = z & (NH - 1);
    float w = __expf(-9.210340371976184f * (float)(64 * h + 2 * j) * (1.0f / 1024.0f));
    float s, c;
    sincosf((float)t * w, &s, &c);
    const float* q = &g_Qf[((size_t)z * TSEQ + t) * HDIM + 2 * j];
    float qa = q[0], qb = q[1];
    float a = qa * s + qb * c;
    float b = qb * s - qa * c;
    size_t o = ((size_t)z * TSEQ + t) * 128 + 64 + 2 * j;
    split_write(g_QAhi, g_QAlo, o, a, b);
}

// ================= smem tile loading (cp.async) =================
#define SROW 72                // 64 data + 8 pad bf16; stride32 = 36
#define TILE_ELEMS (128 * SROW)

__device__ __forceinline__ void ld_tile_async(const __nv_bfloat16* __restrict__ src,
                                              size_t stride,
                                              __nv_bfloat16* __restrict__ dst, int tid) {
#pragma unroll
    for (int it = 0; it < 4; ++it) {
        int idx = tid + it * 256;      // 0..1023
        int r = idx >> 3;              // 0..127
        int c = idx & 7;               // 0..7 (16B chunks)
        cp16(dst + r * SROW + c * 8, src + (size_t)r * stride + c * 8);
    }
}

// ================= big GEMMs (qkv / outproj), cp.async double-buffered ============
// MODE 0: qkv  (emit QA[0:64] bf16, Qf fp32, KB[0:64] bf16, V fp32)
// MODE 1: out  (out = Ctx @ WoutT + bias)
template <int MODE>
__global__ void __launch_bounds__(256, 1) gemm_mma(const float* __restrict__ bias,
                                                   float* __restrict__ outp) {
    extern __shared__ __nv_bfloat16 sm[];   // 2 stages x 4 tiles

    const int tid = threadIdx.x;
    const int wid = tid >> 5, lane = tid & 31;
    const int g = lane >> 2, t = lane & 3;
    const int wm = wid & 1, wn = wid >> 1;
    const int bm = blockIdx.x;                  // token tile   (x128)
    const int bn = blockIdx.y;                  // feature tile (x128)

    const __nv_bfloat16* Agh = (MODE == 0 ? g_Xhi : g_Ctxhi) + (size_t)(bm * 128) * 1024;
    const __nv_bfloat16* Agl = (MODE == 0 ? g_Xlo : g_Ctxlo) + (size_t)(bm * 128) * 1024;
    const __nv_bfloat16* Bgh = (MODE == 0 ? g_WqkvT_hi : g_WoutT_hi) + (size_t)(bn * 128) * 1024;
    const __nv_bfloat16* Bgl = (MODE == 0 ? g_WqkvT_lo : g_WoutT_lo) + (size_t)(bn * 128) * 1024;

    float acc[4][4][4];
#pragma unroll
    for (int mi = 0; mi < 4; mi++)
#pragma unroll
        for (int ni = 0; ni < 4; ni++)
#pragma unroll
            for (int r = 0; r < 4; r++) acc[mi][ni][r] = 0.f;

    auto issue = [&](int kc, int s) {
        __nv_bfloat16* st = sm + s * 4 * TILE_ELEMS;
        ld_tile_async(Agh + kc * 64, 1024, st, tid);
        ld_tile_async(Agl + kc * 64, 1024, st + TILE_ELEMS, tid);
        ld_tile_async(Bgh + kc * 64, 1024, st + 2 * TILE_ELEMS, tid);
        ld_tile_async(Bgl + kc * 64, 1024, st + 3 * TILE_ELEMS, tid);
        CP_COMMIT();
    };

    issue(0, 0);
    for (int kc = 0; kc < 16; kc++) {
        int s = kc & 1;
        if (kc < 15) { issue(kc + 1, s ^ 1); CP_WAIT1(); }
        else         { CP_WAIT0(); }
        __syncthreads();

        const uint32_t* Ah32 = (const uint32_t*)(sm + s * 4 * TILE_ELEMS);
        const uint32_t* Al32 = Ah32 + TILE_ELEMS / 2;
        const uint32_t* Bh32 = Ah32 + TILE_ELEMS;
        const uint32_t* Bl32 = Ah32 + 3 * TILE_ELEMS / 2;

#pragma unroll
        for (int ks = 0; ks < 4; ks++) {
            uint32_t ah[4][4], al[4][4];
#pragma unroll
            for (int mi = 0; mi < 4; mi++) {
                int rb = wm * 64 + mi * 16 + g;
                int o0 = rb * 36 + ks * 8 + t;
                int o1 = (rb + 8) * 36 + ks * 8 + t;
                ah[mi][0] = Ah32[o0];     ah[mi][1] = Ah32[o1];
                ah[mi][2] = Ah32[o0 + 4]; ah[mi][3] = Ah32[o1 + 4];
                al[mi][0] = Al32[o0];     al[mi][1] = Al32[o1];
                al[mi][2] = Al32[o0 + 4]; al[mi][3] = Al32[o1 + 4];
            }
#pragma unroll
            for (int ni = 0; ni < 4; ni++) {
                int nb = wn * 32 + ni * 8 + g;
                int o = nb * 36 + ks * 8 + t;
                uint32_t bh0 = Bh32[o], bh1 = Bh32[o + 4];
                uint32_t bl0 = Bl32[o], bl1 = Bl32[o + 4];
#pragma unroll
                for (int mi = 0; mi < 4; mi++) {
                    mma16816(acc[mi][ni], ah[mi], bh0, bh1);
                    mma16816(acc[mi][ni], ah[mi], bl0, bl1);
                    mma16816(acc[mi][ni], al[mi], bh0, bh1);
                }
            }
        }
        __syncthreads();
    }

    // ---------------- epilogue ----------------
#pragma unroll
    for (int mi = 0; mi < 4; mi++) {
        int m0 = bm * 128 + wm * 64 + mi * 16 + g;
#pragma unroll
        for (int ni = 0; ni < 4; ni++) {
            int n = bn * 128 + wn * 32 + ni * 8 + 2 * t;   // feature col (even)
            float c0 = acc[mi][ni][0], c1 = acc[mi][ni][1];
            float c2 = acc[mi][ni][2], c3 = acc[mi][ni][3];
            if (MODE == 0) {
                int sect = n >> 10, h = (n >> 6) & (NH - 1), hd = n & 63;
                int b0 = m0 >> 11, t0 = m0 & (TSEQ - 1);
                int m1 = m0 + 8, b1 = m1 >> 11, t1 = m1 & (TSEQ - 1);
                size_t z0 = (size_t)b0 * NH + h, z1 = (size_t)b1 * NH + h;
                if (sect == 2) {
                    *(float2*)&g_V[(z0 * TSEQ + t0) * HDIM + hd] = make_float2(c0, c1);
                    *(float2*)&g_V[(z1 * TSEQ + t1) * HDIM + hd] = make_float2(c2, c3);
                } else if (sect == 0) {
                    *(float2*)&g_Qf[(z0 * TSEQ + t0) * HDIM + hd] = make_float2(c0, c1);
                    *(float2*)&g_Qf[(z1 * TSEQ + t1) * HDIM + hd] = make_float2(c2, c3);
                    split_write(g_QAhi, g_QAlo, (z0 * TSEQ + t0) * 128 + hd, c0, c1);
                    split_write(g_QAhi, g_QAlo, (z1 * TSEQ + t1) * 128 + hd, c2, c3);
                } else {
                    split_write(g_KBhi, g_KBlo, (z0 * TSEQ + t0) * 128 + hd, c0, c1);
                    split_write(g_KBhi, g_KBlo, (z1 * TSEQ + t1) * 128 + hd, c2, c3);
                }
            } else {
                float2 bb = *(const float2*)&bias[n];
                *(float2*)&outp[(size_t)m0 * 1024 + n] = make_float2(c0 + bb.x, c1 + bb.y);
                *(float2*)&outp[(size_t)(m0 + 8) * 1024 + n] = make_float2(c2 + bb.x, c3 + bb.y);
            }
        }
    }
}

// ---------------- logits = ([Q|A~]·[K|B~]^T) / 8, causal tiles, K=128 -------------
#define SROWL 136              // 128 data + 8 pad; stride32 = 68
#define LTILE (128 * SROWL)

__device__ __forceinline__ void ld_tile128(const __nv_bfloat16* __restrict__ src,
                                           __nv_bfloat16* __restrict__ dst, int tid) {
#pragma unroll
    for (int it = 0; it < 8; ++it) {
        int idx = tid + it * 256;      // 0..2047
        int r = idx >> 4;              // 0..127
        int c = idx & 15;              // 16B chunks
        cp16(dst + r * SROWL + c * 8, src + (size_t)r * 128 + c * 8);
    }
}

__global__ void __launch_bounds__(256, 1) logits_mma(float* __restrict__ score) {
    // triangular decode: blockIdx.x in [0,136) -> (bm, bn), bn <= bm
    int idx = blockIdx.x;
    int bm = (int)((sqrtf(8.f * idx + 1.f) - 1.f) * 0.5f);
    while ((bm + 1) * (bm + 2) / 2 <= idx) bm++;
    while (bm * (bm + 1) / 2 > idx) bm--;
    int bn = idx - bm * (bm + 1) / 2;
    const int z = blockIdx.y;

    extern __shared__ __nv_bfloat16 sml[];
    __nv_bfloat16* Qh = sml;
    __nv_bfloat16* Ql = sml + LTILE;
    __nv_bfloat16* Kh = sml + 2 * LTILE;
    __nv_bfloat16* Kl = sml + 3 * LTILE;

    const int tid = threadIdx.x;
    const int wid = tid >> 5, lane = tid & 31;
    const int g = lane >> 2, t = lane & 3;
    const int wm = wid & 1, wn = wid >> 1;

    ld_tile128(g_QAhi + ((size_t)z * TSEQ + bm * 128) * 128, Qh, tid);
    ld_tile128(g_QAlo + ((size_t)z * TSEQ + bm * 128) * 128, Ql, tid);
    ld_tile128(g_KBhi + ((size_t)z * TSEQ + bn * 128) * 128, Kh, tid);
    ld_tile128(g_KBlo + ((size_t)z * TSEQ + bn * 128) * 128, Kl, tid);
    CP_COMMIT();
    CP_WAIT0();
    __syncthreads();

    float acc[4][4][4];
#pragma unroll
    for (int mi = 0; mi < 4; mi++)
#pragma unroll
        for (int ni = 0; ni < 4; ni++)
#pragma unroll
            for (int r = 0; r < 4; r++) acc[mi][ni][r] = 0.f;

    const uint32_t* Ah32 = (const uint32_t*)Qh;
    const uint32_t* Al32 = (const uint32_t*)Ql;
    const uint32_t* Bh32 = (const uint32_t*)Kh;
    const uint32_t* Bl32 = (const uint32_t*)Kl;

#pragma unroll
    for (int ks = 0; ks < 8; ks++) {
        uint32_t ah[4][4], al[4][4];
#pragma unroll
        for (int mi = 0; mi < 4; mi++) {
            int rb = wm * 64 + mi * 16 + g;
            int o0 = rb * 68 + ks * 8 + t;
            int o1 = (rb + 8) * 68 + ks * 8 + t;
            ah[mi][0] = Ah32[o0];     ah[mi][1] = Ah32[o1];
            ah[mi][2] = Ah32[o0 + 4]; ah[mi][3] = Ah32[o1 + 4];
            al[mi][0] = Al32[o0];     al[mi][1] = Al32[o1];
            al[mi][2] = Al32[o0 + 4]; al[mi][3] = Al32[o1 + 4];
        }
#pragma unroll
        for (int ni = 0; ni < 4; ni++) {
            int nb = wn * 32 + ni * 8 + g;
            int o = nb * 68 + ks * 8 + t;
            uint32_t bh0 = Bh32[o], bh1 = Bh32[o + 4];
            uint32_t bl0 = Bl32[o], bl1 = Bl32[o + 4];
#pragma unroll
            for (int mi = 0; mi < 4; mi++) {
                mma16816(acc[mi][ni], ah[mi], bh0, bh1);
                mma16816(acc[mi][ni], ah[mi], bl0, bl1);
                mma16816(acc[mi][ni], al[mi], bh0, bh1);
            }
        }
    }

    const float inv_scale = 0.125f;
#pragma unroll
    for (int mi = 0; mi < 4; mi++) {
        int q0 = bm * 128 + wm * 64 + mi * 16 + g;
#pragma unroll
        for (int ni = 0; ni < 4; ni++) {
            int k0 = bn * 128 + wn * 32 + ni * 8 + 2 * t;
            *(float2*)&score[((size_t)z * TSEQ + q0) * TSEQ + k0] =
                make_float2(acc[mi][ni][0] * inv_scale, acc[mi][ni][1] * inv_scale);
            *(float2*)&score[((size_t)z * TSEQ + q0 + 8) * TSEQ + k0] =
                make_float2(acc[mi][ni][2] * inv_scale, acc[mi][ni][3] * inv_scale);
        }
    }
}

// ---------------- causal row softmax, in-place; zeros for k>q ----------------
__global__ void __launch_bounds__(256) softmax_kernel(float* __restrict__ score) {
    size_t row = blockIdx.x;
    int q = (int)(row & (TSEQ - 1));
    float* p = &score[row * TSEQ];
    int tid = threadIdx.x;

    __shared__ float red[8];
    float v[8];
    float mx = -1e30f;
#pragma unroll
    for (int i = 0; i < 8; i++) {
        int k = i * 256 + tid;
        v[i] = -1e30f;
        if (k <= q) { v[i] = p[k]; mx = fmaxf(mx, v[i]); }
    }
#pragma unroll
    for (int o = 16; o > 0; o >>= 1) mx = fmaxf(mx, __shfl_xor_sync(0xffffffffu, mx, o));
    if ((tid & 31) == 0) red[tid >> 5] = mx;
    __syncthreads();
    float bmx = red[0];
#pragma unroll
    for (int w = 1; w < 8; w++) bmx = fmaxf(bmx, red[w]);

    float s = 0.f;
#pragma unroll
    for (int i = 0; i < 8; i++) {
        int k = i * 256 + tid;
        float e = (k <= q) ? __expf(v[i] - bmx) : 0.f;
        v[i] = e;
        s += e;
    }
#pragma unroll
    for (int o = 16; o > 0; o >>= 1) s += __shfl_xor_sync(0xffffffffu, s, o);
    __syncthreads();
    if ((tid & 31) == 0) red[tid >> 5] = s;
    __syncthreads();
    float tot = 0.f;
#pragma unroll
    for (int w = 0; w < 8; w++) tot += red[w];
    float inv = 1.0f / tot;
#pragma unroll
    for (int i = 0; i < 8; i++) {
        int k = i * 256 + tid;
        p[k] = v[i] * inv;
    }
}

// ---------------- ctx = S @ V via mma, cp.async staged, balanced pairs -----------
#define SROW2 136               // stride32 = 68
#define SV_BF16_ELEMS (2 * 128 * SROW2 + 2 * 64 * SROW2)
__global__ void __launch_bounds__(256, 1) sv_mma(const float* __restrict__ score) {
    const int z  = blockIdx.y;
    const int b  = z >> 4, h = z & (NH - 1);

    extern __shared__ __nv_bfloat16 smv[];
    __nv_bfloat16* Sh = smv;
    __nv_bfloat16* Sl = smv + 128 * SROW2;
    __nv_bfloat16* Vh = smv + 2 * 128 * SROW2;     // [64][136] transposed
    __nv_bfloat16* Vl = Vh + 64 * SROW2;
    float* stgS = (float*)(smv + SV_BF16_ELEMS);
    float* stgV = stgS + 128 * 128;

    const int tid = threadIdx.x;
    const int wid = tid >> 5, lane = tid & 31;
    const int g = lane >> 2, t = lane & 3;
    const int wm = wid & 3, wn = wid >> 2;

    uint32_t* Sh32 = (uint32_t*)Sh;
    uint32_t* Sl32 = (uint32_t*)Sl;
    const uint32_t* Vh32 = (const uint32_t*)Vh;
    const uint32_t* Vl32 = (const uint32_t*)Vl;

    for (int rep = 0; rep < 2; rep++) {
        const int bm = rep == 0 ? (int)blockIdx.x : 15 - (int)blockIdx.x;

        float acc[2][4][4];
#pragma unroll
        for (int mi = 0; mi < 2; mi++)
#pragma unroll
            for (int ni = 0; ni < 4; ni++)
#pragma unroll
                for (int r = 0; r < 4; r++) acc[mi][ni][r] = 0.f;

        auto issue_chunk = [&](int kt) {
            const float* Sg = score + ((size_t)z * TSEQ + bm * 128) * TSEQ + kt * 128;
#pragma unroll
            for (int it = 0; it < 16; it++) {
                int idx = tid + it * 256;
                int r = idx >> 5;
                int c4 = idx & 31;
                cp16(stgS + r * 128 + c4 * 4, Sg + (size_t)r * TSEQ + c4 * 4);
            }
            const float* Vg = g_V + ((size_t)z * TSEQ + kt * 128) * HDIM;
#pragma unroll
            for (int it = 0; it < 8; it++) {
                int idx = tid + it * 256;
                int r = idx >> 4;
                int c4 = idx & 15;
                cp16(stgV + r * 64 + c4 * 4, Vg + (size_t)r * HDIM + c4 * 4);
            }
            CP_COMMIT();
        };

        issue_chunk(0);
        for (int kt = 0; kt <= bm; kt++) {
            CP_WAIT0();
            __syncthreads();

#pragma unroll
            for (int it = 0; it < 16; it++) {
                int idx = tid + it * 256;
                int r = idx >> 5;
                int c4 = idx & 31;
                float4 v = *(const float4*)&stgS[r * 128 + c4 * 4];
                __nv_bfloat16 h0 = __float2bfloat16(v.x), h1 = __float2bfloat16(v.y);
                __nv_bfloat16 h2 = __float2bfloat16(v.z), h3 = __float2bfloat16(v.w);
                uint32_t* ph = &Sh32[r * 68 + c4 * 2];
                uint32_t* pl = &Sl32[r * 68 + c4 * 2];
                ph[0] = pack2(h0, h1); ph[1] = pack2(h2, h3);
                pl[0] = pack2(__float2bfloat16(v.x - __bfloat162float(h0)),
                              __float2bfloat16(v.y - __bfloat162float(h1)));
                pl[1] = pack2(__float2bfloat16(v.z - __bfloat162float(h2)),
                              __float2bfloat16(v.w - __bfloat162float(h3)));
            }
#pragma unroll
            for (int it = 0; it < 8; it++) {
                int idx = tid + it * 256;
                int r = idx >> 4;
                int c4 = idx & 15;
                float4 v = *(const float4*)&stgV[r * 64 + c4 * 4];
                float vv[4] = {v.x, v.y, v.z, v.w};
#pragma unroll
                for (int j = 0; j < 4; j++) {
                    __nv_bfloat16 hh = __float2bfloat16(vv[j]);
                    Vh[(c4 * 4 + j) * SROW2 + r] = hh;
                    Vl[(c4 * 4 + j) * SROW2 + r] =
                        __float2bfloat16(vv[j] - __bfloat162float(hh));
                }
            }
            __syncthreads();

            if (kt < bm) issue_chunk(kt + 1);

#pragma unroll
            for (int ks = 0; ks < 8; ks++) {
                uint32_t ah[2][4], al[2][4];
#pragma unroll
                for (int mi = 0; mi < 2; mi++) {
                    int rb = wm * 32 + mi * 16 + g;
                    int o0 = rb * 68 + ks * 8 + t;
                    int o1 = (rb + 8) * 68 + ks * 8 + t;
                    ah[mi][0] = Sh32[o0];     ah[mi][1] = Sh32[o1];
                    ah[mi][2] = Sh32[o0 + 4]; ah[mi][3] = Sh32[o1 + 4];
                    al[mi][0] = Sl32[o0];     al[mi][1] = Sl32[o1];
                    al[mi][2] = Sl32[o0 + 4]; al[mi][3] = Sl32[o1 + 4];
                }
#pragma unroll
                for (int ni = 0; ni < 4; ni++) {
                    int nb = wn * 32 + ni * 8 + g;
                    int o = nb * 68 + ks * 8 + t;
                    uint32_t bh0 = Vh32[o], bh1 = Vh32[o + 4];
                    uint32_t bl0 = Vl32[o], bl1 = Vl32[o + 4];
#pragma unroll
                    for (int mi = 0; mi < 2; mi++) {
                        mma16816(acc[mi][ni], ah[mi], bh0, bh1);
                        mma16816(acc[mi][ni], ah[mi], bl0, bl1);
                        mma16816(acc[mi][ni], al[mi], bh0, bh1);
                    }
                }
            }
            __syncthreads();
        }

        // epilogue: ctx -> bf16 hi/lo [tok][1024]
#pragma unroll
        for (int mi = 0; mi < 2; mi++) {
            int tok0 = bm * 128 + wm * 32 + mi * 16 + g;
#pragma unroll
            for (int ni = 0; ni < 4; ni++) {
                int n = wn * 32 + ni * 8 + 2 * t;
                size_t o0 = ((size_t)b * TSEQ + tok0) * DMODEL + h * HDIM + n;
                size_t o1 = ((size_t)b * TSEQ + tok0 + 8) * DMODEL + h * HDIM + n;
                split_write(g_Ctxhi, g_Ctxlo, o0, acc[mi][ni][0], acc[mi][ni][1]);
                split_write(g_Ctxhi, g_Ctxlo, o1, acc[mi][ni][2], acc[mi][ni][3]);
            }
        }
    }
}

// ---------------- launch ----------------
extern "C" void kernel_launch(void* const* d_in, const int* in_sizes, int n_in,
                              void* d_out, int out_size) {
    const float* x    = (const float*)d_in[0];   // [B,T,D]
    const float* Wqkv = (const float*)d_in[2];   // [D,3D]
    const float* Wout = (const float*)d_in[3];   // [D,D]
    const float* bout = (const float*)d_in[4];   // [D]

    float* out = (float*)d_out;
    const size_t outElems = (size_t)BATCH * TSEQ * DMODEL;
    const size_t scoreElems = (size_t)BH * TSEQ * TSEQ;
    float* score = ((size_t)out_size >= outElems + scoreElems)
                       ? (out + outElems)
                       : g_scoreScratch;

    const int TILE1_SMEM = 4 * TILE_ELEMS * (int)sizeof(__nv_bfloat16);       // 73728
    const int GEMM_SMEM = 2 * TILE1_SMEM;                                     // 147456
    const int LOGITS_SMEM = 4 * LTILE * (int)sizeof(__nv_bfloat16);           // 139264
    const int SV_SMEM = SV_BF16_ELEMS * (int)sizeof(__nv_bfloat16)
                        + (128 * 128 + 128 * 64) * (int)sizeof(float);        // 202752
    cudaFuncSetAttribute(gemm_mma<0>, cudaFuncAttributeMaxDynamicSharedMemorySize, GEMM_SMEM);
    cudaFuncSetAttribute(gemm_mma<1>, cudaFuncAttributeMaxDynamicSharedMemorySize, GEMM_SMEM);
    cudaFuncSetAttribute(logits_mma, cudaFuncAttributeMaxDynamicSharedMemorySize, LOGITS_SMEM);
    cudaFuncSetAttribute(sv_mma,     cudaFuncAttributeMaxDynamicSharedMemorySize, SV_SMEM);

    __nv_bfloat16 *xhi, *xlo, *wqh, *wql, *woh, *wol;
    cudaGetSymbolAddress((void**)&xhi, g_Xhi);
    cudaGetSymbolAddress((void**)&xlo, g_Xlo);
    cudaGetSymbolAddress((void**)&wqh, g_WqkvT_hi);
    cudaGetSymbolAddress((void**)&wql, g_WqkvT_lo);
    cudaGetSymbolAddress((void**)&woh, g_WoutT_hi);
    cudaGetSymbolAddress((void**)&wol, g_WoutT_lo);

    split_kernel<<<(4096 * 1024) / 256, 256>>>(x, xhi, xlo);
    transpose_split_kernel<<<dim3(3072 / 32, 1024 / 32), dim3(32, 8)>>>(Wqkv, wqh, wql, 3072);
    transpose_split_kernel<<<dim3(1024 / 32, 1024 / 32), dim3(32, 8)>>>(Wout, woh, wol, 1024);
    kb_kernel<<<(BH * TSEQ * 32) / 256, 256>>>();                      // B~ table

    gemm_mma<0><<<dim3(32, 24), 256, GEMM_SMEM>>>(nullptr, nullptr);   // QKV

    ae_kernel<<<(BH * TSEQ * 32) / 256, 256>>>();                      // A~ from Q

    logits_mma<<<dim3(136, 32), 256, LOGITS_SMEM>>>(score);
    softmax_kernel<<<BH * TSEQ, 256>>>(score);
    sv_mma<<<dim3(8, 32), 256, SV_SMEM>>>(score);

    gemm_mma<1><<<dim3(32, 8), 256, GEMM_SMEM>>>(bout, out);           // out proj
}